// round 4
// baseline (speedup 1.0000x reference)
#include <cuda_runtime.h>
#include <cuda_bf16.h>
#include <math.h>

#define NN 100000
#define EE 3200000

// ---------------- device scratch (no runtime allocation) ----------------
__device__ __align__(16) float g_H[32 * NN];        // [q][n] transposed
__device__ __align__(16) float g_Pd[NN * 64];       // [n][i][2] pairs (to,fr)
__device__ __align__(16) float g_Ps[NN * 64];       // [n][i][2] pairs (to,fr)
__device__ __align__(16) float g_sum_to[NN * 32];   // [n][j]
__device__ __align__(16) float g_sum_fr[NN * 32];   // [n][j]
__device__ int   g_cnt_to[NN];
__device__ int   g_cnt_fr[NN];
__device__ float g_selfsum[NN];
__device__ float g_loss[4];

// packed/folded weights
__device__ __align__(16) float g_G[96 * 132];       // GRU folded matrix [q][132]
__device__ float g_bias[96];                        // bih + Wih_lp@lpb2 (+bhh r,z)
__device__ float g_cto[96];                         // Wih_mto@to_b2
__device__ float g_cfr[96];                         // Wih_mfr@fr_b2

// ---------------- init ----------------
__global__ void k_init() {
    int t = blockIdx.x * blockDim.x + threadIdx.x;
    int nt = gridDim.x * blockDim.x;
    for (int i = t; i < 32 * NN; i += nt) g_H[i] = 0.f;
    for (int i = t; i < NN; i += nt) {
        g_cnt_to[i] = 0; g_cnt_fr[i] = 0; g_selfsum[i] = 0.f;
    }
    if (t < 4) g_loss[t] = 0.f;
}

// counts + self-loop sums (H-independent; once per replay)
__global__ void k_count(const int* __restrict__ ei, const float* __restrict__ ea) {
    int e = blockIdx.x * blockDim.x + threadIdx.x;
    if (e >= EE) return;
    int s = ei[e];
    int d = ei[EE + e];
    if (s != d) {
        atomicAdd(&g_cnt_to[d], 1);
        atomicAdd(&g_cnt_fr[s], 1);
    } else {
        atomicAdd(&g_selfsum[s], ea[2 * e]);
    }
}

// ---------------- weight folding ----------------
__global__ void k_pack(const float* __restrict__ Wih, const float* __restrict__ bih,
                       const float* __restrict__ bhh,
                       const float* __restrict__ toW2, const float* __restrict__ tob2,
                       const float* __restrict__ frW2, const float* __restrict__ frb2,
                       const float* __restrict__ lpW2, const float* __restrict__ lpb2) {
    int t = blockIdx.x * blockDim.x + threadIdx.x;
    int nt = gridDim.x * blockDim.x;
    for (int idx = t; idx < 96 * 132; idx += nt) {
        int q = idx / 132, c = idx - q * 132;
        float v = 0.f;
        if (c < 32) {
            v = Wih[q * 131 + c];                                   // H block
        } else if (c < 64) {
            int j = c - 32;                                          // m_to block folded
            for (int i = 0; i < 32; i++) v += Wih[q * 131 + 32 + i] * toW2[i * 32 + j];
        } else if (c < 96) {
            int j = c - 64;                                          // m_fr block folded
            for (int i = 0; i < 32; i++) v += Wih[q * 131 + 64 + i] * frW2[i * 32 + j];
        } else if (c < 128) {
            int j = c - 96;                                          // lp layer2 folded
            for (int i = 0; i < 32; i++) v += Wih[q * 131 + 96 + i] * lpW2[i * 32 + j];
        } else if (c < 131) {
            v = Wih[q * 131 + 128 + (c - 128)];                      // x block
        }
        g_G[idx] = v;
    }
    for (int q = t; q < 96; q += nt) {
        float b = bih[q], ct = 0.f, cf = 0.f;
        for (int i = 0; i < 32; i++) {
            b  += Wih[q * 131 + 96 + i] * lpb2[i];
            ct += Wih[q * 131 + 32 + i] * tob2[i];
            cf += Wih[q * 131 + 64 + i] * frb2[i];
        }
        if (q < 64) b += bhh[q];   // fold b_hr / b_hz; b_hn handled inside tanh
        g_bias[q] = b; g_cto[q] = ct; g_cfr[q] = cf;
    }
}

// ---------------- per-node projections + decode/loss + sum zeroing ----------------
__global__ __launch_bounds__(128) void k_proj(
        const float* __restrict__ toW1, const float* __restrict__ frW1,
        const float* __restrict__ dec1, const float* __restrict__ decb1,
        const float* __restrict__ dec2, const float* __restrict__ decb2,
        const float* __restrict__ y, float* __restrict__ outF,
        int compute_proj, int loss_idx) {
    __shared__ float sPA[4096];    // [m][i][j]: m0=A_to, m1=B_fr (Pd); m2=B_to, m3=A_fr (Ps)
    __shared__ float sD1[1024];
    __shared__ float sD2[64];
    __shared__ float sDb1[32];
    __shared__ float sDb2[2];

    for (int i = threadIdx.x; i < 4096; i += 128) {
        int m = i >> 10, r = i & 1023, ii = r >> 5, j = r & 31;
        float v;
        if (m == 0)      v = toW1[ii * 66 + j];
        else if (m == 1) v = frW1[ii * 66 + 32 + j];
        else if (m == 2) v = toW1[ii * 66 + 32 + j];
        else             v = frW1[ii * 66 + j];
        sPA[i] = v;
    }
    for (int i = threadIdx.x; i < 1024; i += 128) sD1[i] = dec1[i];
    if (threadIdx.x < 64) sD2[threadIdx.x] = dec2[threadIdx.x];
    if (threadIdx.x < 32) sDb1[threadIdx.x] = decb1[threadIdx.x];
    if (threadIdx.x < 2)  sDb2[threadIdx.x] = decb2[threadIdx.x];
    __syncthreads();

    int n = blockIdx.x * 128 + threadIdx.x;
    bool act = n < NN;

    float h[32];
#pragma unroll
    for (int j = 0; j < 32; j++) h[j] = act ? g_H[j * NN + n] : 0.f;

    if (act && compute_proj) {
        for (int i = 0; i < 32; i++) {            // rolled
            float a0 = 0.f, a1 = 0.f, a2 = 0.f, a3 = 0.f;
#pragma unroll
            for (int j = 0; j < 32; j++) {
                float hj = h[j];
                a0 += sPA[i * 32 + j] * hj;
                a1 += sPA[1024 + i * 32 + j] * hj;
                a2 += sPA[2048 + i * 32 + j] * hj;
                a3 += sPA[3072 + i * 32 + j] * hj;
            }
            *(float2*)&g_Pd[n * 64 + i * 2] = make_float2(a0, a1);
            *(float2*)&g_Ps[n * 64 + i * 2] = make_float2(a2, a3);
        }
        float4 z4 = make_float4(0.f, 0.f, 0.f, 0.f);
#pragma unroll
        for (int j4 = 0; j4 < 8; j4++) {
            *(float4*)&g_sum_to[n * 32 + j4 * 4] = z4;
            *(float4*)&g_sum_fr[n * 32 + j4 * 4] = z4;
        }
    }

    if (loss_idx >= 0) {
        float sse = 0.f;
        float F0 = sDb2[0], F1 = sDb2[1];
        for (int i = 0; i < 32; i++) {            // rolled
            float a = sDb1[i];
#pragma unroll
            for (int j = 0; j < 32; j++) a += sD1[i * 32 + j] * h[j];
            a = fmaxf(a, 0.f);
            F0 += sD2[i] * a;
            F1 += sD2[32 + i] * a;
        }
        if (act) {
            float d0 = F0 - y[n * 2], d1 = F1 - y[n * 2 + 1];
            sse = d0 * d0 + d1 * d1;
            if (outF) { outF[n * 2] = F0; outF[n * 2 + 1] = F1; }
        }
#pragma unroll
        for (int o = 16; o; o >>= 1) sse += __shfl_down_sync(0xffffffffu, sse, o);
        if ((threadIdx.x & 31) == 0) atomicAdd(&g_loss[loss_idx], sse);
    }
}

// ---------------- edge kernel: gather + relu + scatter-add ----------------
__global__ __launch_bounds__(256) void k_edge(
        const int* __restrict__ ei, const float* __restrict__ ea,
        const float* __restrict__ toW1, const float* __restrict__ tob1,
        const float* __restrict__ frW1, const float* __restrict__ frb1) {
    int lane = threadIdx.x & 31;
    int warp = (blockIdx.x * 256 + threadIdx.x) >> 5;
    float wT0 = __ldg(&toW1[lane * 66 + 64]);
    float wT1 = __ldg(&toW1[lane * 66 + 65]);
    float wF0 = __ldg(&frW1[lane * 66 + 64]);
    float wF1 = __ldg(&frW1[lane * 66 + 65]);
    float bT  = __ldg(&tob1[lane]);
    float bF  = __ldg(&frb1[lane]);
    int e0 = warp * 4;
#pragma unroll
    for (int k = 0; k < 4; k++) {
        int e = e0 + k;
        if (e >= EE) break;
        int s = __ldg(&ei[e]);
        int d = __ldg(&ei[EE + e]);
        if (s == d) continue;
        float ea0 = __ldg(&ea[2 * e]);
        float ea1 = __ldg(&ea[2 * e + 1]);
        float2 pd = *(const float2*)&g_Pd[d * 64 + lane * 2];
        float2 ps = *(const float2*)&g_Ps[s * 64 + lane * 2];
        float zt = fmaxf(pd.x + ps.x + ea0 * wT0 + ea1 * wT1 + bT, 0.f);
        float zf = fmaxf(pd.y + ps.y + ea0 * wF0 + ea1 * wF1 + bF, 0.f);
        atomicAdd(&g_sum_to[d * 32 + lane], zt);
        atomicAdd(&g_sum_fr[s * 32 + lane], zf);
    }
}

// ---------------- node kernel: means + lp + folded GRU + H update ----------------
__global__ __launch_bounds__(128) void k_node(
        const float* __restrict__ x,
        const float* __restrict__ lpW1, const float* __restrict__ lpb1,
        const float* __restrict__ bhh) {
    extern __shared__ float sm[];
    float* sG   = sm;              // 96*132 = 12672
    float* sb   = sG + 12672;      // 96
    float* sct  = sb + 96;         // 96
    float* scf  = sct + 96;        // 96
    float* sbhn = scf + 96;        // 32
    float* sW1f = sbhn + 32;       // 32*36 = 1152
    float* sb1  = sW1f + 1152;     // 32

    for (int i = threadIdx.x; i < 12672; i += 128) sG[i] = g_G[i];
    for (int i = threadIdx.x; i < 96; i += 128) {
        sb[i] = g_bias[i]; sct[i] = g_cto[i]; scf[i] = g_cfr[i];
    }
    if (threadIdx.x < 32) {
        sbhn[threadIdx.x] = bhh[64 + threadIdx.x];
        sb1[threadIdx.x]  = lpb1[threadIdx.x];
    }
    for (int i = threadIdx.x; i < 32 * 36; i += 128) {
        int tq = i / 36, c = i - tq * 36;
        float v = 0.f;
        if (c < 32)       v = lpW1[tq * 65 + c] + lpW1[tq * 65 + 32 + c];
        else if (c == 32) v = lpW1[tq * 65 + 64];
        sW1f[i] = v;
    }
    __syncthreads();

    int n = blockIdx.x * 128 + threadIdx.x;
    if (n >= NN) return;

    float vH[32];
#pragma unroll
    for (int j = 0; j < 32; j++) vH[j] = g_H[j * NN + n];

    int ct = g_cnt_to[n], cf = g_cnt_fr[n];
    float rt = ct > 0 ? 1.f / (float)ct : 0.f;
    float rf = cf > 0 ? 1.f / (float)cf : 0.f;

    float vmt[32], vmf[32];
#pragma unroll
    for (int j4 = 0; j4 < 8; j4++) {
        float4 a = *(const float4*)&g_sum_to[n * 32 + j4 * 4];
        vmt[j4 * 4] = a.x * rt; vmt[j4 * 4 + 1] = a.y * rt;
        vmt[j4 * 4 + 2] = a.z * rt; vmt[j4 * 4 + 3] = a.w * rt;
        float4 b = *(const float4*)&g_sum_fr[n * 32 + j4 * 4];
        vmf[j4 * 4] = b.x * rf; vmf[j4 * 4 + 1] = b.y * rf;
        vmf[j4 * 4 + 2] = b.z * rf; vmf[j4 * 4 + 3] = b.w * rf;
    }

    float lc = -g_selfsum[n];   // loop_col = 1 - diag = -selfsum
    float vt1[32];
#pragma unroll
    for (int i = 0; i < 32; i++) {
        float a = sb1[i] + sW1f[i * 36 + 32] * lc;
#pragma unroll
        for (int j = 0; j < 32; j++) a += sW1f[i * 36 + j] * vH[j];
        vt1[i] = fmaxf(a, 0.f);
    }

    float x0 = x[n * 3], x1 = x[n * 3 + 1], x2 = x[n * 3 + 2];

    for (int qc = 0; qc < 16; qc++) {   // rolled: 2 GRU rows per chunk
        int q0 = qc * 2;
        float aR0 = sb[q0],     aR1 = sb[q0 + 1];
        float aZ0 = sb[32 + q0], aZ1 = sb[33 + q0];
        float aN0 = sb[64 + q0], aN1 = sb[65 + q0];
        if (ct > 0) {
            aR0 += sct[q0]; aR1 += sct[q0 + 1];
            aZ0 += sct[32 + q0]; aZ1 += sct[33 + q0];
            aN0 += sct[64 + q0]; aN1 += sct[65 + q0];
        }
        if (cf > 0) {
            aR0 += scf[q0]; aR1 += scf[q0 + 1];
            aZ0 += scf[32 + q0]; aZ1 += scf[33 + q0];
            aN0 += scf[64 + q0]; aN1 += scf[65 + q0];
        }
#pragma unroll
        for (int j4 = 0; j4 < 33; j4++) {
            float v0, v1, v2, v3;
            if (j4 < 8)       { int b = j4 * 4;        v0 = vH[b];  v1 = vH[b+1];  v2 = vH[b+2];  v3 = vH[b+3]; }
            else if (j4 < 16) { int b = (j4 - 8) * 4;  v0 = vmt[b]; v1 = vmt[b+1]; v2 = vmt[b+2]; v3 = vmt[b+3]; }
            else if (j4 < 24) { int b = (j4 - 16) * 4; v0 = vmf[b]; v1 = vmf[b+1]; v2 = vmf[b+2]; v3 = vmf[b+3]; }
            else if (j4 < 32) { int b = (j4 - 24) * 4; v0 = vt1[b]; v1 = vt1[b+1]; v2 = vt1[b+2]; v3 = vt1[b+3]; }
            else              { v0 = x0; v1 = x1; v2 = x2; v3 = 0.f; }
            float4 w;
            w = *(const float4*)&sG[(q0)      * 132 + j4 * 4]; aR0 += w.x*v0 + w.y*v1 + w.z*v2 + w.w*v3;
            w = *(const float4*)&sG[(q0 + 1)  * 132 + j4 * 4]; aR1 += w.x*v0 + w.y*v1 + w.z*v2 + w.w*v3;
            w = *(const float4*)&sG[(32 + q0) * 132 + j4 * 4]; aZ0 += w.x*v0 + w.y*v1 + w.z*v2 + w.w*v3;
            w = *(const float4*)&sG[(33 + q0) * 132 + j4 * 4]; aZ1 += w.x*v0 + w.y*v1 + w.z*v2 + w.w*v3;
            w = *(const float4*)&sG[(64 + q0) * 132 + j4 * 4]; aN0 += w.x*v0 + w.y*v1 + w.z*v2 + w.w*v3;
            w = *(const float4*)&sG[(65 + q0) * 132 + j4 * 4]; aN1 += w.x*v0 + w.y*v1 + w.z*v2 + w.w*v3;
        }
#pragma unroll
        for (int i = 0; i < 2; i++) {
            int q = q0 + i;
            float aR = i ? aR1 : aR0;
            float aZ = i ? aZ1 : aZ0;
            float aN = i ? aN1 : aN0;
            float r = 1.f / (1.f + __expf(-aR));
            float z = 1.f / (1.f + __expf(-aZ));
            float tn = aN + r * sbhn[q];
            float th = 2.f / (1.f + __expf(-2.f * tn)) - 1.f;   // tanh
            float gru = (1.f - z) * th;
            int off = q * NN + n;
            g_H[off] = g_H[off] + 0.5f * gru;                   // ALPHA = 0.5
        }
    }
}

// ---------------- finalize losses ----------------
__global__ void k_final(float* __restrict__ out) {
    if (blockIdx.x == 0 && threadIdx.x == 0) {
        float inv = 1.f / (2.f * (float)NN);
        float l0 = g_loss[0] * inv;
        float l1 = g_loss[1] * inv;
        float l2 = g_loss[2] * inv;
        float l3 = g_loss[3] * inv;
        out[200000] = 0.729f * l0 + 0.81f * l1 + 0.9f * l2 + l3;
        out[200001] = l0; out[200002] = l1; out[200003] = l2; out[200004] = l3;
    }
}

// ---------------- launch ----------------
extern "C" void kernel_launch(void* const* d_in, const int* in_sizes, int n_in,
                              void* d_out, int out_size) {
    const float* x    = (const float*)d_in[0];
    const float* y    = (const float*)d_in[1];
    const int*   ei   = (const int*)d_in[2];
    const float* ea   = (const float*)d_in[3];
    const float* toW1 = (const float*)d_in[4];
    const float* tob1 = (const float*)d_in[5];
    const float* toW2 = (const float*)d_in[6];
    const float* tob2 = (const float*)d_in[7];
    const float* frW1 = (const float*)d_in[8];
    const float* frb1 = (const float*)d_in[9];
    const float* frW2 = (const float*)d_in[10];
    const float* frb2 = (const float*)d_in[11];
    const float* lpW1 = (const float*)d_in[12];
    const float* lpb1 = (const float*)d_in[13];
    const float* lpW2 = (const float*)d_in[14];
    const float* lpb2 = (const float*)d_in[15];
    const float* Wih  = (const float*)d_in[16];
    const float* bih  = (const float*)d_in[17];
    // d_in[18] = gru_Whh (unused: h0 = 0)
    const float* bhh  = (const float*)d_in[19];
    const float* dec1 = (const float*)d_in[20];
    const float* decb1= (const float*)d_in[21];
    const float* dec2 = (const float*)d_in[22];
    const float* decb2= (const float*)d_in[23];
    float* out = (float*)d_out;

    const int node_smem = 14176 * 4;   // 56704 bytes
    cudaFuncSetAttribute(k_node, cudaFuncAttributeMaxDynamicSharedMemorySize, node_smem);

    k_init<<<1024, 256>>>();
    k_count<<<(EE + 255) / 256, 256>>>(ei, ea);
    k_pack<<<8, 256>>>(Wih, bih, bhh, toW2, tob2, frW2, frb2, lpW2, lpb2);

    int nblk = (NN + 127) / 128;
    for (int step = 0; step < 4; step++) {
        k_proj<<<nblk, 128>>>(toW1, frW1, dec1, decb1, dec2, decb2, y,
                              nullptr, 1, step - 1);
        k_edge<<<EE / 32, 256>>>(ei, ea, toW1, tob1, frW1, frb1);
        k_node<<<nblk, 128, node_smem>>>(x, lpW1, lpb1, bhh);
    }
    k_proj<<<nblk, 128>>>(toW1, frW1, dec1, decb1, dec2, decb2, y, out, 0, 3);
    k_final<<<1, 32>>>(out);
}

// round 5
// speedup vs baseline: 1.7071x; 1.7071x over previous
#include <cuda_runtime.h>
#include <cuda_bf16.h>
#include <math.h>

#define NN 100000
#define EE 3200000

// ---------------- device scratch (no runtime allocation) ----------------
__device__ __align__(16) float g_H[32 * NN];       // [q][n] transposed
__device__ __align__(16) float g_Pdt[NN * 32];     // toW1[:, :32]  @ H[d]
__device__ __align__(16) float g_Pdf[NN * 32];     // frW1[:,32:64] @ H[d]
__device__ __align__(16) float g_Pst[NN * 32];     // toW1[:,32:64] @ H[s]
__device__ __align__(16) float g_Psf[NN * 32];     // frW1[:, :32]  @ H[s]
__device__ __align__(16) float g_sum_to[NN * 32];  // [n][j]
__device__ __align__(16) float g_sum_fr[NN * 32];  // [n][j]
__device__ int   g_cnt_to[NN];
__device__ int   g_cnt_fr[NN];
__device__ float g_selfsum[NN];
__device__ float g_loss[4];

// packed/folded weights
__device__ __align__(16) float g_G[96 * 132];      // GRU folded matrix [q][132]
__device__ float g_bias[96];
__device__ float g_cto[96];
__device__ float g_cfr[96];
__device__ __align__(16) float g_ew[192];          // [6][32]: wT0,wT1,bT,wF0,wF1,bF

// ---------------- init ----------------
__global__ void k_init() {
    int t = blockIdx.x * blockDim.x + threadIdx.x;
    int nt = gridDim.x * blockDim.x;
    for (int i = t; i < 32 * NN; i += nt) {
        g_H[i] = 0.f;
        g_Pdt[i] = 0.f; g_Pdf[i] = 0.f; g_Pst[i] = 0.f; g_Psf[i] = 0.f;
        g_sum_to[i] = 0.f; g_sum_fr[i] = 0.f;
    }
    for (int i = t; i < NN; i += nt) {
        g_cnt_to[i] = 0; g_cnt_fr[i] = 0; g_selfsum[i] = 0.f;
    }
    if (t < 4) g_loss[t] = 0.f;
}

// counts + self-loop sums (H-independent)
__global__ void k_count(const int* __restrict__ ei, const float* __restrict__ ea) {
    int e = blockIdx.x * blockDim.x + threadIdx.x;
    if (e >= EE) return;
    int s = ei[e];
    int d = ei[EE + e];
    if (s != d) {
        atomicAdd(&g_cnt_to[d], 1);
        atomicAdd(&g_cnt_fr[s], 1);
    } else {
        atomicAdd(&g_selfsum[s], ea[2 * e]);
    }
}

// ---------------- weight folding ----------------
__global__ void k_pack(const float* __restrict__ Wih, const float* __restrict__ bih,
                       const float* __restrict__ bhh,
                       const float* __restrict__ toW2, const float* __restrict__ tob2,
                       const float* __restrict__ frW2, const float* __restrict__ frb2,
                       const float* __restrict__ lpW2, const float* __restrict__ lpb2,
                       const float* __restrict__ toW1, const float* __restrict__ tob1,
                       const float* __restrict__ frW1, const float* __restrict__ frb1) {
    int t = blockIdx.x * blockDim.x + threadIdx.x;
    int nt = gridDim.x * blockDim.x;
    for (int idx = t; idx < 96 * 132; idx += nt) {
        int q = idx / 132, c = idx - q * 132;
        float v = 0.f;
        if (c < 32) {
            v = Wih[q * 131 + c];
        } else if (c < 64) {
            int j = c - 32;
            for (int i = 0; i < 32; i++) v += Wih[q * 131 + 32 + i] * toW2[i * 32 + j];
        } else if (c < 96) {
            int j = c - 64;
            for (int i = 0; i < 32; i++) v += Wih[q * 131 + 64 + i] * frW2[i * 32 + j];
        } else if (c < 128) {
            int j = c - 96;
            for (int i = 0; i < 32; i++) v += Wih[q * 131 + 96 + i] * lpW2[i * 32 + j];
        } else if (c < 131) {
            v = Wih[q * 131 + 128 + (c - 128)];
        }
        g_G[idx] = v;
    }
    for (int q = t; q < 96; q += nt) {
        float b = bih[q], ct = 0.f, cf = 0.f;
        for (int i = 0; i < 32; i++) {
            b  += Wih[q * 131 + 96 + i] * lpb2[i];
            ct += Wih[q * 131 + 32 + i] * tob2[i];
            cf += Wih[q * 131 + 64 + i] * frb2[i];
        }
        if (q < 64) b += bhh[q];
        g_bias[q] = b; g_cto[q] = ct; g_cfr[q] = cf;
    }
    for (int i = t; i < 192; i += nt) {
        int r = i >> 5, j = i & 31;
        float v;
        if      (r == 0) v = toW1[j * 66 + 64];
        else if (r == 1) v = toW1[j * 66 + 65];
        else if (r == 2) v = tob1[j];
        else if (r == 3) v = frW1[j * 66 + 64];
        else if (r == 4) v = frW1[j * 66 + 65];
        else             v = frb1[j];
        g_ew[i] = v;
    }
}

// ---------------- edge kernel: 8-lane groups, float4 gather + vector red ----------------
__device__ __forceinline__ void red4(float* p, float4 v) {
    asm volatile("red.global.add.v4.f32 [%0], {%1, %2, %3, %4};"
                 :: "l"(p), "f"(v.x), "f"(v.y), "f"(v.z), "f"(v.w) : "memory");
}

__global__ __launch_bounds__(256) void k_edge(const int* __restrict__ ei,
                                              const float* __restrict__ ea) {
    __shared__ float sw[192];
    if (threadIdx.x < 192) sw[threadIdx.x] = g_ew[threadIdx.x];
    __syncthreads();
    int lane = threadIdx.x & 31;
    int g = lane >> 3;
    int c4 = (lane & 7) * 4;
    float4 wt0 = *(float4*)&sw[c4];
    float4 wt1 = *(float4*)&sw[32 + c4];
    float4 bt  = *(float4*)&sw[64 + c4];
    float4 wf0 = *(float4*)&sw[96 + c4];
    float4 wf1 = *(float4*)&sw[128 + c4];
    float4 bf  = *(float4*)&sw[160 + c4];
    int warp = (blockIdx.x * 256 + threadIdx.x) >> 5;
    int base = warp * 16 + g;
#pragma unroll
    for (int k = 0; k < 4; k++) {
        int e = base + k * 4;
        int s = __ldg(&ei[e]);
        int d = __ldg(&ei[EE + e]);
        if (s == d) continue;
        float2 a = *(const float2*)&ea[2 * e];
        float4 pdt = *(const float4*)&g_Pdt[d * 32 + c4];
        float4 pdf = *(const float4*)&g_Pdf[d * 32 + c4];
        float4 pst = *(const float4*)&g_Pst[s * 32 + c4];
        float4 psf = *(const float4*)&g_Psf[s * 32 + c4];
        float4 zt, zf;
        zt.x = fmaxf(pdt.x + pst.x + a.x * wt0.x + a.y * wt1.x + bt.x, 0.f);
        zt.y = fmaxf(pdt.y + pst.y + a.x * wt0.y + a.y * wt1.y + bt.y, 0.f);
        zt.z = fmaxf(pdt.z + pst.z + a.x * wt0.z + a.y * wt1.z + bt.z, 0.f);
        zt.w = fmaxf(pdt.w + pst.w + a.x * wt0.w + a.y * wt1.w + bt.w, 0.f);
        zf.x = fmaxf(pdf.x + psf.x + a.x * wf0.x + a.y * wf1.x + bf.x, 0.f);
        zf.y = fmaxf(pdf.y + psf.y + a.x * wf0.y + a.y * wf1.y + bf.y, 0.f);
        zf.z = fmaxf(pdf.z + psf.z + a.x * wf0.z + a.y * wf1.z + bf.z, 0.f);
        zf.w = fmaxf(pdf.w + psf.w + a.x * wf0.w + a.y * wf1.w + bf.w, 0.f);
        red4(&g_sum_to[d * 32 + c4], zt);
        red4(&g_sum_fr[s * 32 + c4], zf);
    }
}

// ---------------- fused node kernel: means + lp + GRU + H, then proj + decode + loss ----------------
__global__ __launch_bounds__(128) void k_node(
        const float* __restrict__ x,
        const float* __restrict__ lpW1, const float* __restrict__ lpb1,
        const float* __restrict__ bhh,
        const float* __restrict__ toW1, const float* __restrict__ frW1,
        const float* __restrict__ dec1, const float* __restrict__ decb1,
        const float* __restrict__ dec2, const float* __restrict__ decb2,
        const float* __restrict__ y, float* __restrict__ outF,
        int do_proj, int loss_idx) {
    extern __shared__ float sm[];
    float* sG   = sm;              // 12672
    float* sb   = sG + 12672;      // 96
    float* sct  = sb + 96;         // 96
    float* scf  = sct + 96;        // 96
    float* sbhn = scf + 96;        // 32
    float* sW1f = sbhn + 32;       // 1152
    float* sb1  = sW1f + 1152;     // 32
    float* sPA  = sb1 + 32;        // 4096
    float* sD1  = sPA + 4096;      // 1024
    float* sD2  = sD1 + 1024;      // 64
    float* sDb1 = sD2 + 64;        // 32
    float* sDb2 = sDb1 + 32;       // 2

    for (int i = threadIdx.x; i < 12672; i += 128) sG[i] = g_G[i];
    for (int i = threadIdx.x; i < 96; i += 128) {
        sb[i] = g_bias[i]; sct[i] = g_cto[i]; scf[i] = g_cfr[i];
    }
    if (threadIdx.x < 32) {
        sbhn[threadIdx.x] = bhh[64 + threadIdx.x];
        sb1[threadIdx.x]  = lpb1[threadIdx.x];
    }
    for (int i = threadIdx.x; i < 32 * 36; i += 128) {
        int tq = i / 36, c = i - tq * 36;
        float v = 0.f;
        if (c < 32)       v = lpW1[tq * 65 + c] + lpW1[tq * 65 + 32 + c];
        else if (c == 32) v = lpW1[tq * 65 + 64];
        sW1f[i] = v;
    }
    for (int i = threadIdx.x; i < 4096; i += 128) {
        int m = i >> 10, r = i & 1023, ii = r >> 5, j = r & 31;
        float v;
        if (m == 0)      v = toW1[ii * 66 + j];        // Pdt
        else if (m == 1) v = frW1[ii * 66 + 32 + j];   // Pdf
        else if (m == 2) v = toW1[ii * 66 + 32 + j];   // Pst
        else             v = frW1[ii * 66 + j];        // Psf
        sPA[i] = v;
    }
    for (int i = threadIdx.x; i < 1024; i += 128) sD1[i] = dec1[i];
    if (threadIdx.x < 64) sD2[threadIdx.x] = dec2[threadIdx.x];
    if (threadIdx.x < 32) sDb1[threadIdx.x] = decb1[threadIdx.x];
    if (threadIdx.x < 2)  sDb2[threadIdx.x] = decb2[threadIdx.x];
    __syncthreads();

    int n = blockIdx.x * 128 + threadIdx.x;
    if (n >= NN) return;

    float vH[32];
#pragma unroll
    for (int j = 0; j < 32; j++) vH[j] = g_H[j * NN + n];

    int ct = g_cnt_to[n], cf = g_cnt_fr[n];
    float rt = ct > 0 ? 1.f / (float)ct : 0.f;
    float rf = cf > 0 ? 1.f / (float)cf : 0.f;

    float vmt[32], vmf[32];
#pragma unroll
    for (int j4 = 0; j4 < 8; j4++) {
        float4 a = *(const float4*)&g_sum_to[n * 32 + j4 * 4];
        vmt[j4 * 4] = a.x * rt; vmt[j4 * 4 + 1] = a.y * rt;
        vmt[j4 * 4 + 2] = a.z * rt; vmt[j4 * 4 + 3] = a.w * rt;
        float4 b = *(const float4*)&g_sum_fr[n * 32 + j4 * 4];
        vmf[j4 * 4] = b.x * rf; vmf[j4 * 4 + 1] = b.y * rf;
        vmf[j4 * 4 + 2] = b.z * rf; vmf[j4 * 4 + 3] = b.w * rf;
    }

    float lc = -g_selfsum[n];   // loop_col = 1 - diag = -selfsum
    float vt1[32];
#pragma unroll
    for (int i = 0; i < 32; i++) {
        float a = sb1[i] + sW1f[i * 36 + 32] * lc;
#pragma unroll
        for (int j = 0; j < 32; j++) a += sW1f[i * 36 + j] * vH[j];
        vt1[i] = fmaxf(a, 0.f);
    }

    float x0 = x[n * 3], x1 = x[n * 3 + 1], x2 = x[n * 3 + 2];

    for (int qc = 0; qc < 16; qc++) {   // 2 GRU rows per chunk
        int q0 = qc * 2;
        float aR0 = sb[q0],      aR1 = sb[q0 + 1];
        float aZ0 = sb[32 + q0], aZ1 = sb[33 + q0];
        float aN0 = sb[64 + q0], aN1 = sb[65 + q0];
        if (ct > 0) {
            aR0 += sct[q0]; aR1 += sct[q0 + 1];
            aZ0 += sct[32 + q0]; aZ1 += sct[33 + q0];
            aN0 += sct[64 + q0]; aN1 += sct[65 + q0];
        }
        if (cf > 0) {
            aR0 += scf[q0]; aR1 += scf[q0 + 1];
            aZ0 += scf[32 + q0]; aZ1 += scf[33 + q0];
            aN0 += scf[64 + q0]; aN1 += scf[65 + q0];
        }
#pragma unroll
        for (int j4 = 0; j4 < 33; j4++) {
            float v0, v1, v2, v3;
            if (j4 < 8)       { int b = j4 * 4;        v0 = vH[b];  v1 = vH[b+1];  v2 = vH[b+2];  v3 = vH[b+3]; }
            else if (j4 < 16) { int b = (j4 - 8) * 4;  v0 = vmt[b]; v1 = vmt[b+1]; v2 = vmt[b+2]; v3 = vmt[b+3]; }
            else if (j4 < 24) { int b = (j4 - 16) * 4; v0 = vmf[b]; v1 = vmf[b+1]; v2 = vmf[b+2]; v3 = vmf[b+3]; }
            else if (j4 < 32) { int b = (j4 - 24) * 4; v0 = vt1[b]; v1 = vt1[b+1]; v2 = vt1[b+2]; v3 = vt1[b+3]; }
            else              { v0 = x0; v1 = x1; v2 = x2; v3 = 0.f; }
            float4 w;
            w = *(const float4*)&sG[(q0)      * 132 + j4 * 4]; aR0 += w.x*v0 + w.y*v1 + w.z*v2 + w.w*v3;
            w = *(const float4*)&sG[(q0 + 1)  * 132 + j4 * 4]; aR1 += w.x*v0 + w.y*v1 + w.z*v2 + w.w*v3;
            w = *(const float4*)&sG[(32 + q0) * 132 + j4 * 4]; aZ0 += w.x*v0 + w.y*v1 + w.z*v2 + w.w*v3;
            w = *(const float4*)&sG[(33 + q0) * 132 + j4 * 4]; aZ1 += w.x*v0 + w.y*v1 + w.z*v2 + w.w*v3;
            w = *(const float4*)&sG[(64 + q0) * 132 + j4 * 4]; aN0 += w.x*v0 + w.y*v1 + w.z*v2 + w.w*v3;
            w = *(const float4*)&sG[(65 + q0) * 132 + j4 * 4]; aN1 += w.x*v0 + w.y*v1 + w.z*v2 + w.w*v3;
        }
#pragma unroll
        for (int i = 0; i < 2; i++) {
            int q = q0 + i;
            float aR = i ? aR1 : aR0;
            float aZ = i ? aZ1 : aZ0;
            float aN = i ? aN1 : aN0;
            float r = 1.f / (1.f + __expf(-aR));
            float z = 1.f / (1.f + __expf(-aZ));
            float tn = aN + r * sbhn[q];
            float th = 2.f / (1.f + __expf(-2.f * tn)) - 1.f;
            float gru = (1.f - z) * th;
            int off = q * NN + n;
            g_H[off] = g_H[off] + 0.5f * gru;    // ALPHA = 0.5
        }
    }

    // reload updated H (L2-hot) for proj + decode
#pragma unroll
    for (int j = 0; j < 32; j++) vH[j] = g_H[j * NN + n];

    if (do_proj) {
        for (int i = 0; i < 32; i++) {
            float a0 = 0.f, a1 = 0.f, a2 = 0.f, a3 = 0.f;
#pragma unroll
            for (int j = 0; j < 32; j++) {
                float hj = vH[j];
                a0 += sPA[i * 32 + j] * hj;
                a1 += sPA[1024 + i * 32 + j] * hj;
                a2 += sPA[2048 + i * 32 + j] * hj;
                a3 += sPA[3072 + i * 32 + j] * hj;
            }
            g_Pdt[n * 32 + i] = a0;
            g_Pdf[n * 32 + i] = a1;
            g_Pst[n * 32 + i] = a2;
            g_Psf[n * 32 + i] = a3;
        }
        float4 z4 = make_float4(0.f, 0.f, 0.f, 0.f);
#pragma unroll
        for (int j4 = 0; j4 < 8; j4++) {
            *(float4*)&g_sum_to[n * 32 + j4 * 4] = z4;
            *(float4*)&g_sum_fr[n * 32 + j4 * 4] = z4;
        }
    }

    // decode + loss
    {
        float F0 = sDb2[0], F1 = sDb2[1];
        for (int i = 0; i < 32; i++) {
            float a = sDb1[i];
#pragma unroll
            for (int j = 0; j < 32; j++) a += sD1[i * 32 + j] * vH[j];
            a = fmaxf(a, 0.f);
            F0 += sD2[i] * a;
            F1 += sD2[32 + i] * a;
        }
        float d0 = F0 - y[n * 2], d1 = F1 - y[n * 2 + 1];
        float sse = d0 * d0 + d1 * d1;
        if (outF) { outF[n * 2] = F0; outF[n * 2 + 1] = F1; }
#pragma unroll
        for (int o = 16; o; o >>= 1) sse += __shfl_down_sync(0xffffffffu, sse, o);
        if ((threadIdx.x & 31) == 0) atomicAdd(&g_loss[loss_idx], sse);
    }
}

// ---------------- finalize losses ----------------
__global__ void k_final(float* __restrict__ out) {
    if (blockIdx.x == 0 && threadIdx.x == 0) {
        float inv = 1.f / (2.f * (float)NN);
        float l0 = g_loss[0] * inv;
        float l1 = g_loss[1] * inv;
        float l2 = g_loss[2] * inv;
        float l3 = g_loss[3] * inv;
        out[200000] = 0.729f * l0 + 0.81f * l1 + 0.9f * l2 + l3;
        out[200001] = l0; out[200002] = l1; out[200003] = l2; out[200004] = l3;
    }
}

// ---------------- launch ----------------
extern "C" void kernel_launch(void* const* d_in, const int* in_sizes, int n_in,
                              void* d_out, int out_size) {
    const float* x    = (const float*)d_in[0];
    const float* y    = (const float*)d_in[1];
    const int*   ei   = (const int*)d_in[2];
    const float* ea   = (const float*)d_in[3];
    const float* toW1 = (const float*)d_in[4];
    const float* tob1 = (const float*)d_in[5];
    const float* toW2 = (const float*)d_in[6];
    const float* tob2 = (const float*)d_in[7];
    const float* frW1 = (const float*)d_in[8];
    const float* frb1 = (const float*)d_in[9];
    const float* frW2 = (const float*)d_in[10];
    const float* frb2 = (const float*)d_in[11];
    const float* lpW1 = (const float*)d_in[12];
    const float* lpb1 = (const float*)d_in[13];
    const float* lpW2 = (const float*)d_in[14];
    const float* lpb2 = (const float*)d_in[15];
    const float* Wih  = (const float*)d_in[16];
    const float* bih  = (const float*)d_in[17];
    // d_in[18] = gru_Whh (unused: h0 = 0)
    const float* bhh  = (const float*)d_in[19];
    const float* dec1 = (const float*)d_in[20];
    const float* decb1= (const float*)d_in[21];
    const float* dec2 = (const float*)d_in[22];
    const float* decb2= (const float*)d_in[23];
    float* out = (float*)d_out;

    const int node_smem = 19394 * 4;   // 77576 bytes
    cudaFuncSetAttribute(k_node, cudaFuncAttributeMaxDynamicSharedMemorySize, node_smem);

    k_init<<<1024, 256>>>();
    k_count<<<(EE + 255) / 256, 256>>>(ei, ea);
    k_pack<<<8, 256>>>(Wih, bih, bhh, toW2, tob2, frW2, frb2, lpW2, lpb2,
                       toW1, tob1, frW1, frb1);

    int nblk = (NN + 127) / 128;
    for (int step = 0; step < 4; step++) {
        k_edge<<<EE / 128, 256>>>(ei, ea);
        k_node<<<nblk, 128, node_smem>>>(x, lpW1, lpb1, bhh, toW1, frW1,
                                         dec1, decb1, dec2, decb2, y,
                                         (step == 3) ? out : nullptr,
                                         (step < 3) ? 1 : 0, step);
    }
    k_final<<<1, 32>>>(out);
}

// round 6
// speedup vs baseline: 1.7416x; 1.0202x over previous
#include <cuda_runtime.h>
#include <cuda_fp16.h>
#include <math.h>

#define NN 100000
#define EE 3200000

typedef unsigned long long u64;

__device__ __forceinline__ u64 pk(float a, float b) {
    u64 r; asm("mov.b64 %0,{%1,%2};" : "=l"(r) : "f"(a), "f"(b)); return r;
}
__device__ __forceinline__ void upk(u64 v, float& a, float& b) {
    asm("mov.b64 {%0,%1},%2;" : "=f"(a), "=f"(b) : "l"(v));
}
__device__ __forceinline__ void ffma2(u64& d, u64 a, u64 b) {
    asm("fma.rn.f32x2 %0,%1,%2,%0;" : "+l"(d) : "l"(a), "l"(b));
}

// ---------------- device scratch ----------------
__device__ __align__(16) float   g_H[32 * NN];      // [q][n]
__device__ __align__(16) __half2 g_Pd[NN * 32];     // [n][j]: x=to(dst part), y=fr(dst part)
__device__ __align__(16) __half2 g_Ps[NN * 32];     // [n][j]: x=to(src part), y=fr(src part)
__device__ __align__(16) float g_sum_to[NN * 32];
__device__ __align__(16) float g_sum_fr[NN * 32];
__device__ int   g_cnt_to[NN];
__device__ int   g_cnt_fr[NN];
__device__ float g_selfsum[NN];
__device__ float g_loss[4];

// packed/folded weights
__device__ __align__(16) float g_G[96 * 132];
__device__ float g_bias[96];
__device__ float g_cto[96];
__device__ float g_cfr[96];
__device__ __align__(16) float g_ew[192];           // wT0,wT1,bT,wF0,wF1,bF

// ---------------- init ----------------
__global__ void k_init() {
    int t = blockIdx.x * blockDim.x + threadIdx.x;
    int nt = gridDim.x * blockDim.x;
    __half2 hz = __floats2half2_rn(0.f, 0.f);
    for (int i = t; i < 32 * NN; i += nt) {
        g_H[i] = 0.f;
        g_Pd[i] = hz; g_Ps[i] = hz;
        g_sum_to[i] = 0.f; g_sum_fr[i] = 0.f;
    }
    for (int i = t; i < NN; i += nt) {
        g_cnt_to[i] = 0; g_cnt_fr[i] = 0; g_selfsum[i] = 0.f;
    }
    if (t < 4) g_loss[t] = 0.f;
}

__global__ void k_count(const int* __restrict__ ei, const float* __restrict__ ea) {
    int e = blockIdx.x * blockDim.x + threadIdx.x;
    if (e >= EE) return;
    int s = ei[e];
    int d = ei[EE + e];
    if (s != d) {
        atomicAdd(&g_cnt_to[d], 1);
        atomicAdd(&g_cnt_fr[s], 1);
    } else {
        atomicAdd(&g_selfsum[s], ea[2 * e]);
    }
}

// ---------------- weight folding ----------------
__global__ void k_pack(const float* __restrict__ Wih, const float* __restrict__ bih,
                       const float* __restrict__ bhh,
                       const float* __restrict__ toW2, const float* __restrict__ tob2,
                       const float* __restrict__ frW2, const float* __restrict__ frb2,
                       const float* __restrict__ lpW2, const float* __restrict__ lpb2,
                       const float* __restrict__ toW1, const float* __restrict__ tob1,
                       const float* __restrict__ frW1, const float* __restrict__ frb1) {
    int t = blockIdx.x * blockDim.x + threadIdx.x;
    int nt = gridDim.x * blockDim.x;
    for (int idx = t; idx < 96 * 132; idx += nt) {
        int q = idx / 132, c = idx - q * 132;
        float v = 0.f;
        if (c < 32) {
            v = Wih[q * 131 + c];
        } else if (c < 64) {
            int j = c - 32;
            for (int i = 0; i < 32; i++) v += Wih[q * 131 + 32 + i] * toW2[i * 32 + j];
        } else if (c < 96) {
            int j = c - 64;
            for (int i = 0; i < 32; i++) v += Wih[q * 131 + 64 + i] * frW2[i * 32 + j];
        } else if (c < 128) {
            int j = c - 96;
            for (int i = 0; i < 32; i++) v += Wih[q * 131 + 96 + i] * lpW2[i * 32 + j];
        } else if (c < 131) {
            v = Wih[q * 131 + 128 + (c - 128)];
        }
        g_G[idx] = v;
    }
    for (int q = t; q < 96; q += nt) {
        float b = bih[q], ct = 0.f, cf = 0.f;
        for (int i = 0; i < 32; i++) {
            b  += Wih[q * 131 + 96 + i] * lpb2[i];
            ct += Wih[q * 131 + 32 + i] * tob2[i];
            cf += Wih[q * 131 + 64 + i] * frb2[i];
        }
        if (q < 64) b += bhh[q];
        g_bias[q] = b; g_cto[q] = ct; g_cfr[q] = cf;
    }
    for (int i = t; i < 192; i += nt) {
        int r = i >> 5, j = i & 31;
        float v;
        if      (r == 0) v = toW1[j * 66 + 64];
        else if (r == 1) v = toW1[j * 66 + 65];
        else if (r == 2) v = tob1[j];
        else if (r == 3) v = frW1[j * 66 + 64];
        else if (r == 4) v = frW1[j * 66 + 65];
        else             v = frb1[j];
        g_ew[i] = v;
    }
}

// ---------------- edge kernel: fp16 interleaved gather + vector red ----------------
__device__ __forceinline__ void red4(float* p, float4 v) {
    asm volatile("red.global.add.v4.f32 [%0], {%1, %2, %3, %4};"
                 :: "l"(p), "f"(v.x), "f"(v.y), "f"(v.z), "f"(v.w) : "memory");
}

__global__ __launch_bounds__(256) void k_edge(const int* __restrict__ ei,
                                              const float* __restrict__ ea) {
    __shared__ float sw[192];
    if (threadIdx.x < 192) sw[threadIdx.x] = g_ew[threadIdx.x];
    __syncthreads();
    int lane = threadIdx.x & 31;
    int g = lane >> 3;
    int c4 = (lane & 7) * 4;
    float4 wt0 = *(float4*)&sw[c4];
    float4 wt1 = *(float4*)&sw[32 + c4];
    float4 bt  = *(float4*)&sw[64 + c4];
    float4 wf0 = *(float4*)&sw[96 + c4];
    float4 wf1 = *(float4*)&sw[128 + c4];
    float4 bf  = *(float4*)&sw[160 + c4];
    int warp = (blockIdx.x * 256 + threadIdx.x) >> 5;
    int base = warp * 16 + g;
#pragma unroll
    for (int k = 0; k < 4; k++) {
        int e = base + k * 4;
        int s = __ldg(&ei[e]);
        int d = __ldg(&ei[EE + e]);
        if (s == d) continue;
        float2 a = *(const float2*)&ea[2 * e];
        uint4 pd4 = *(const uint4*)&g_Pd[d * 32 + c4];
        uint4 ps4 = *(const uint4*)&g_Ps[s * 32 + c4];
        float2 d0 = __half22float2(*(__half2*)&pd4.x);
        float2 d1 = __half22float2(*(__half2*)&pd4.y);
        float2 d2 = __half22float2(*(__half2*)&pd4.z);
        float2 d3 = __half22float2(*(__half2*)&pd4.w);
        float2 s0 = __half22float2(*(__half2*)&ps4.x);
        float2 s1 = __half22float2(*(__half2*)&ps4.y);
        float2 s2 = __half22float2(*(__half2*)&ps4.z);
        float2 s3 = __half22float2(*(__half2*)&ps4.w);
        float4 zt, zf;
        zt.x = fmaxf(d0.x + s0.x + a.x * wt0.x + a.y * wt1.x + bt.x, 0.f);
        zt.y = fmaxf(d1.x + s1.x + a.x * wt0.y + a.y * wt1.y + bt.y, 0.f);
        zt.z = fmaxf(d2.x + s2.x + a.x * wt0.z + a.y * wt1.z + bt.z, 0.f);
        zt.w = fmaxf(d3.x + s3.x + a.x * wt0.w + a.y * wt1.w + bt.w, 0.f);
        zf.x = fmaxf(d0.y + s0.y + a.x * wf0.x + a.y * wf1.x + bf.x, 0.f);
        zf.y = fmaxf(d1.y + s1.y + a.x * wf0.y + a.y * wf1.y + bf.y, 0.f);
        zf.z = fmaxf(d2.y + s2.y + a.x * wf0.z + a.y * wf1.z + bf.z, 0.f);
        zf.w = fmaxf(d3.y + s3.y + a.x * wf0.w + a.y * wf1.w + bf.w, 0.f);
        red4(&g_sum_to[d * 32 + c4], zt);
        red4(&g_sum_fr[s * 32 + c4], zf);
    }
}

// ---------------- fused node kernel (f32x2 packed math) ----------------
__global__ __launch_bounds__(128) void k_node(
        const float* __restrict__ x,
        const float* __restrict__ lpW1, const float* __restrict__ lpb1,
        const float* __restrict__ bhh,
        const float* __restrict__ toW1, const float* __restrict__ frW1,
        const float* __restrict__ dec1, const float* __restrict__ decb1,
        const float* __restrict__ dec2, const float* __restrict__ decb2,
        const float* __restrict__ y, float* __restrict__ outF,
        int do_proj, int loss_idx) {
    extern __shared__ float sm[];
    float* sG   = sm;              // 12672
    float* sb   = sG + 12672;      // 96
    float* sct  = sb + 96;         // 96
    float* scf  = sct + 96;        // 96
    float* sbhn = scf + 96;        // 32
    float* sW1f = sbhn + 32;       // 1152 (stride 36)
    float* sb1  = sW1f + 1152;     // 32
    float* sPA  = sb1 + 32;        // 4096
    float* sD1  = sPA + 4096;      // 1024
    float* sD2  = sD1 + 1024;      // 64
    float* sDb1 = sD2 + 64;        // 32
    float* sDb2 = sDb1 + 32;       // 2

    for (int i = threadIdx.x; i < 12672; i += 128) sG[i] = g_G[i];
    for (int i = threadIdx.x; i < 96; i += 128) {
        sb[i] = g_bias[i]; sct[i] = g_cto[i]; scf[i] = g_cfr[i];
    }
    if (threadIdx.x < 32) {
        sbhn[threadIdx.x] = bhh[64 + threadIdx.x];
        sb1[threadIdx.x]  = lpb1[threadIdx.x];
    }
    for (int i = threadIdx.x; i < 32 * 36; i += 128) {
        int tq = i / 36, c = i - tq * 36;
        float v = 0.f;
        if (c < 32)       v = lpW1[tq * 65 + c] + lpW1[tq * 65 + 32 + c];
        else if (c == 32) v = lpW1[tq * 65 + 64];
        sW1f[i] = v;
    }
    for (int i = threadIdx.x; i < 4096; i += 128) {
        int m = i >> 10, r = i & 1023, ii = r >> 5, j = r & 31;
        float v;
        if (m == 0)      v = toW1[ii * 66 + j];        // Pd.to
        else if (m == 1) v = frW1[ii * 66 + 32 + j];   // Pd.fr
        else if (m == 2) v = toW1[ii * 66 + 32 + j];   // Ps.to
        else             v = frW1[ii * 66 + j];        // Ps.fr
        sPA[i] = v;
    }
    for (int i = threadIdx.x; i < 1024; i += 128) sD1[i] = dec1[i];
    if (threadIdx.x < 64) sD2[threadIdx.x] = dec2[threadIdx.x];
    if (threadIdx.x < 32) sDb1[threadIdx.x] = decb1[threadIdx.x];
    if (threadIdx.x < 2)  sDb2[threadIdx.x] = decb2[threadIdx.x];
    __syncthreads();

    int n = blockIdx.x * 128 + threadIdx.x;
    if (n >= NN) return;

    u64 vHp[16];
#pragma unroll
    for (int k = 0; k < 16; k++)
        vHp[k] = pk(g_H[(2 * k) * NN + n], g_H[(2 * k + 1) * NN + n]);

    int ct = g_cnt_to[n], cf = g_cnt_fr[n];
    float rt = ct > 0 ? 1.f / (float)ct : 0.f;
    float rf = cf > 0 ? 1.f / (float)cf : 0.f;

    u64 vmtp[16], vmfp[16];
#pragma unroll
    for (int j4 = 0; j4 < 8; j4++) {
        float4 a = *(const float4*)&g_sum_to[n * 32 + j4 * 4];
        vmtp[j4 * 2]     = pk(a.x * rt, a.y * rt);
        vmtp[j4 * 2 + 1] = pk(a.z * rt, a.w * rt);
        float4 b = *(const float4*)&g_sum_fr[n * 32 + j4 * 4];
        vmfp[j4 * 2]     = pk(b.x * rf, b.y * rf);
        vmfp[j4 * 2 + 1] = pk(b.z * rf, b.w * rf);
    }

    float lc = -g_selfsum[n];   // loop_col = 1 - diag = -selfsum
    u64 vt1p[16];
#pragma unroll
    for (int i2 = 0; i2 < 16; i2++) {
        int i0 = 2 * i2;
        u64 acc0 = pk(sb1[i0]     + sW1f[i0 * 36 + 32] * lc, 0.f);
        u64 acc1 = pk(sb1[i0 + 1] + sW1f[(i0 + 1) * 36 + 32] * lc, 0.f);
#pragma unroll
        for (int j4 = 0; j4 < 8; j4++) {
            ulonglong2 w0 = *(const ulonglong2*)&sW1f[i0 * 36 + j4 * 4];
            ulonglong2 w1 = *(const ulonglong2*)&sW1f[(i0 + 1) * 36 + j4 * 4];
            ffma2(acc0, w0.x, vHp[j4 * 2]); ffma2(acc0, w0.y, vHp[j4 * 2 + 1]);
            ffma2(acc1, w1.x, vHp[j4 * 2]); ffma2(acc1, w1.y, vHp[j4 * 2 + 1]);
        }
        float a0, b0, a1, b1;
        upk(acc0, a0, b0); upk(acc1, a1, b1);
        vt1p[i2] = pk(fmaxf(a0 + b0, 0.f), fmaxf(a1 + b1, 0.f));
    }

    float x0 = x[n * 3], x1 = x[n * 3 + 1], x2 = x[n * 3 + 2];
    u64 xlo = pk(x0, x1), xhi = pk(x2, 0.f);

    for (int qc = 0; qc < 16; qc++) {
        int q0 = qc * 2;
        float bR0 = sb[q0],      bR1 = sb[q0 + 1];
        float bZ0 = sb[32 + q0], bZ1 = sb[33 + q0];
        float bN0 = sb[64 + q0], bN1 = sb[65 + q0];
        if (ct > 0) {
            bR0 += sct[q0]; bR1 += sct[q0 + 1];
            bZ0 += sct[32 + q0]; bZ1 += sct[33 + q0];
            bN0 += sct[64 + q0]; bN1 += sct[65 + q0];
        }
        if (cf > 0) {
            bR0 += scf[q0]; bR1 += scf[q0 + 1];
            bZ0 += scf[32 + q0]; bZ1 += scf[33 + q0];
            bN0 += scf[64 + q0]; bN1 += scf[65 + q0];
        }
        u64 AR0 = pk(bR0, 0.f), AR1 = pk(bR1, 0.f);
        u64 AZ0 = pk(bZ0, 0.f), AZ1 = pk(bZ1, 0.f);
        u64 AN0 = pk(bN0, 0.f), AN1 = pk(bN1, 0.f);
#pragma unroll
        for (int j4 = 0; j4 < 33; j4++) {
            u64 vlo, vhi;
            if (j4 < 8)       { vlo = vHp[j4 * 2];          vhi = vHp[j4 * 2 + 1]; }
            else if (j4 < 16) { vlo = vmtp[(j4 - 8) * 2];   vhi = vmtp[(j4 - 8) * 2 + 1]; }
            else if (j4 < 24) { vlo = vmfp[(j4 - 16) * 2];  vhi = vmfp[(j4 - 16) * 2 + 1]; }
            else if (j4 < 32) { vlo = vt1p[(j4 - 24) * 2];  vhi = vt1p[(j4 - 24) * 2 + 1]; }
            else              { vlo = xlo; vhi = xhi; }
            ulonglong2 w;
            w = *(const ulonglong2*)&sG[(q0)      * 132 + j4 * 4]; ffma2(AR0, w.x, vlo); ffma2(AR0, w.y, vhi);
            w = *(const ulonglong2*)&sG[(q0 + 1)  * 132 + j4 * 4]; ffma2(AR1, w.x, vlo); ffma2(AR1, w.y, vhi);
            w = *(const ulonglong2*)&sG[(32 + q0) * 132 + j4 * 4]; ffma2(AZ0, w.x, vlo); ffma2(AZ0, w.y, vhi);
            w = *(const ulonglong2*)&sG[(33 + q0) * 132 + j4 * 4]; ffma2(AZ1, w.x, vlo); ffma2(AZ1, w.y, vhi);
            w = *(const ulonglong2*)&sG[(64 + q0) * 132 + j4 * 4]; ffma2(AN0, w.x, vlo); ffma2(AN0, w.y, vhi);
            w = *(const ulonglong2*)&sG[(65 + q0) * 132 + j4 * 4]; ffma2(AN1, w.x, vlo); ffma2(AN1, w.y, vhi);
        }
#pragma unroll
        for (int i = 0; i < 2; i++) {
            int q = q0 + i;
            float lo, hi;
            upk(i ? AR1 : AR0, lo, hi); float aR = lo + hi;
            upk(i ? AZ1 : AZ0, lo, hi); float aZ = lo + hi;
            upk(i ? AN1 : AN0, lo, hi); float aN = lo + hi;
            float r = 1.f / (1.f + __expf(-aR));
            float z = 1.f / (1.f + __expf(-aZ));
            float tn = aN + r * sbhn[q];
            float th = 2.f / (1.f + __expf(-2.f * tn)) - 1.f;
            float gru = (1.f - z) * th;
            int off = q * NN + n;
            g_H[off] = g_H[off] + 0.5f * gru;    // ALPHA = 0.5
        }
    }

    // reload updated H (L2-hot)
#pragma unroll
    for (int k = 0; k < 16; k++)
        vHp[k] = pk(g_H[(2 * k) * NN + n], g_H[(2 * k + 1) * NN + n]);

    if (do_proj) {
        for (int i4 = 0; i4 < 8; i4++) {
            u64 A[16];
#pragma unroll
            for (int t = 0; t < 16; t++) A[t] = 0ull;   // (0.f, 0.f)
#pragma unroll
            for (int j4 = 0; j4 < 8; j4++) {
                u64 vlo = vHp[j4 * 2], vhi = vHp[j4 * 2 + 1];
#pragma unroll
                for (int m = 0; m < 4; m++) {
#pragma unroll
                    for (int ii = 0; ii < 4; ii++) {
                        ulonglong2 w = *(const ulonglong2*)&sPA[m * 1024 + (i4 * 4 + ii) * 32 + j4 * 4];
                        ffma2(A[m * 4 + ii], w.x, vlo);
                        ffma2(A[m * 4 + ii], w.y, vhi);
                    }
                }
            }
            uint4 pdst, psst;
            unsigned* pdp = &pdst.x;
            unsigned* psp = &psst.x;
#pragma unroll
            for (int ii = 0; ii < 4; ii++) {
                float lo, hi;
                upk(A[ii], lo, hi);      float vdt = lo + hi;   // Pd.to
                upk(A[4 + ii], lo, hi);  float vdf = lo + hi;   // Pd.fr
                upk(A[8 + ii], lo, hi);  float vst = lo + hi;   // Ps.to
                upk(A[12 + ii], lo, hi); float vsf = lo + hi;   // Ps.fr
                __half2 hd = __floats2half2_rn(vdt, vdf);
                __half2 hs = __floats2half2_rn(vst, vsf);
                pdp[ii] = *(unsigned*)&hd;
                psp[ii] = *(unsigned*)&hs;
            }
            *(uint4*)&g_Pd[n * 32 + i4 * 4] = pdst;
            *(uint4*)&g_Ps[n * 32 + i4 * 4] = psst;
        }
        float4 z4 = make_float4(0.f, 0.f, 0.f, 0.f);
#pragma unroll
        for (int j4 = 0; j4 < 8; j4++) {
            *(float4*)&g_sum_to[n * 32 + j4 * 4] = z4;
            *(float4*)&g_sum_fr[n * 32 + j4 * 4] = z4;
        }
    }

    // decode + loss
    {
        float F0 = sDb2[0], F1 = sDb2[1];
        for (int i = 0; i < 32; i++) {
            u64 acc = pk(sDb1[i], 0.f);
#pragma unroll
            for (int j4 = 0; j4 < 8; j4++) {
                ulonglong2 w = *(const ulonglong2*)&sD1[i * 32 + j4 * 4];
                ffma2(acc, w.x, vHp[j4 * 2]);
                ffma2(acc, w.y, vHp[j4 * 2 + 1]);
            }
            float lo, hi; upk(acc, lo, hi);
            float a = fmaxf(lo + hi, 0.f);
            F0 += sD2[i] * a;
            F1 += sD2[32 + i] * a;
        }
        float d0 = F0 - y[n * 2], d1 = F1 - y[n * 2 + 1];
        float sse = d0 * d0 + d1 * d1;
        if (outF) { outF[n * 2] = F0; outF[n * 2 + 1] = F1; }
#pragma unroll
        for (int o = 16; o; o >>= 1) sse += __shfl_down_sync(0xffffffffu, sse, o);
        if ((threadIdx.x & 31) == 0) atomicAdd(&g_loss[loss_idx], sse);
    }
}

// ---------------- finalize losses ----------------
__global__ void k_final(float* __restrict__ out) {
    if (blockIdx.x == 0 && threadIdx.x == 0) {
        float inv = 1.f / (2.f * (float)NN);
        float l0 = g_loss[0] * inv;
        float l1 = g_loss[1] * inv;
        float l2 = g_loss[2] * inv;
        float l3 = g_loss[3] * inv;
        out[200000] = 0.729f * l0 + 0.81f * l1 + 0.9f * l2 + l3;
        out[200001] = l0; out[200002] = l1; out[200003] = l2; out[200004] = l3;
    }
}

// ---------------- launch ----------------
extern "C" void kernel_launch(void* const* d_in, const int* in_sizes, int n_in,
                              void* d_out, int out_size) {
    const float* x    = (const float*)d_in[0];
    const float* y    = (const float*)d_in[1];
    const int*   ei   = (const int*)d_in[2];
    const float* ea   = (const float*)d_in[3];
    const float* toW1 = (const float*)d_in[4];
    const float* tob1 = (const float*)d_in[5];
    const float* toW2 = (const float*)d_in[6];
    const float* tob2 = (const float*)d_in[7];
    const float* frW1 = (const float*)d_in[8];
    const float* frb1 = (const float*)d_in[9];
    const float* frW2 = (const float*)d_in[10];
    const float* frb2 = (const float*)d_in[11];
    const float* lpW1 = (const float*)d_in[12];
    const float* lpb1 = (const float*)d_in[13];
    const float* lpW2 = (const float*)d_in[14];
    const float* lpb2 = (const float*)d_in[15];
    const float* Wih  = (const float*)d_in[16];
    const float* bih  = (const float*)d_in[17];
    // d_in[18] = gru_Whh (unused: h0 = 0)
    const float* bhh  = (const float*)d_in[19];
    const float* dec1 = (const float*)d_in[20];
    const float* decb1= (const float*)d_in[21];
    const float* dec2 = (const float*)d_in[22];
    const float* decb2= (const float*)d_in[23];
    float* out = (float*)d_out;

    const int node_smem = 19394 * 4;   // 77576 bytes
    cudaFuncSetAttribute(k_node, cudaFuncAttributeMaxDynamicSharedMemorySize, node_smem);

    k_init<<<1024, 256>>>();
    k_count<<<(EE + 255) / 256, 256>>>(ei, ea);
    k_pack<<<8, 256>>>(Wih, bih, bhh, toW2, tob2, frW2, frb2, lpW2, lpb2,
                       toW1, tob1, frW1, frb1);

    int nblk = (NN + 127) / 128;
    for (int step = 0; step < 4; step++) {
        k_edge<<<EE / 128, 256>>>(ei, ea);
        k_node<<<nblk, 128, node_smem>>>(x, lpW1, lpb1, bhh, toW1, frW1,
                                         dec1, decb1, dec2, decb2, y,
                                         (step == 3) ? out : nullptr,
                                         (step < 3) ? 1 : 0, step);
    }
    k_final<<<1, 32>>>(out);
}

// round 7
// speedup vs baseline: 2.0797x; 1.1941x over previous
#include <cuda_runtime.h>
#include <cuda_fp16.h>
#include <math.h>

#define NN 100000
#define EE 3200000
#define NB 98   // ceil(NN/1024)

typedef unsigned long long u64;

__device__ __forceinline__ u64 pk(float a, float b) {
    u64 r; asm("mov.b64 %0,{%1,%2};" : "=l"(r) : "f"(a), "f"(b)); return r;
}
__device__ __forceinline__ void upk(u64 v, float& a, float& b) {
    asm("mov.b64 {%0,%1},%2;" : "=f"(a), "=f"(b) : "l"(v));
}
__device__ __forceinline__ void ffma2(u64& d, u64 a, u64 b) {
    asm("fma.rn.f32x2 %0,%1,%2,%0;" : "+l"(d) : "l"(a), "l"(b));
}

// ---------------- device scratch ----------------
__device__ __align__(16) float  g_H[32 * NN];       // [q][n]
__device__ __align__(16) __half g_PdtH[NN * 32];    // toW1[:, :32]  @ H  (stationary, pass-to)
__device__ __align__(16) __half g_PdfH[NN * 32];    // frW1[:,32:64] @ H  (gathered,  pass-fr)
__device__ __align__(16) __half g_PstH[NN * 32];    // toW1[:,32:64] @ H  (gathered,  pass-to)
__device__ __align__(16) __half g_PsfH[NN * 32];    // frW1[:, :32]  @ H  (stationary, pass-fr)
__device__ __align__(16) float g_sum_to[NN * 32];
__device__ __align__(16) float g_sum_fr[NN * 32];
__device__ int   g_cnt_to[NN];
__device__ int   g_cnt_fr[NN];
__device__ float g_selfsum[NN];
__device__ float g_loss[4];

// CSR
__device__ int g_rowp_to[NN + 1];
__device__ int g_rowp_fr[NN + 1];
__device__ int g_cur_to[NN];
__device__ int g_cur_fr[NN];
__device__ u64 g_pay_to[EE];    // low32: src idx, high32: half2(ea)
__device__ u64 g_pay_fr[EE];    // low32: dst idx, high32: half2(ea)
__device__ int g_blks[2 * NB];

// packed/folded weights
__device__ __align__(16) float g_G[96 * 132];
__device__ float g_bias[96];
__device__ float g_cto[96];
__device__ float g_cfr[96];
__device__ __align__(16) float g_ew[192];   // rows: wT0,wT1,bT,wF0,wF1,bF

// ---------------- init ----------------
__global__ void k_init() {
    int t = blockIdx.x * blockDim.x + threadIdx.x;
    int nt = gridDim.x * blockDim.x;
    __half hz = __float2half(0.f);
    for (int i = t; i < 32 * NN; i += nt) {
        g_H[i] = 0.f;
        g_PdtH[i] = hz; g_PdfH[i] = hz; g_PstH[i] = hz; g_PsfH[i] = hz;
    }
    for (int i = t; i < NN; i += nt) {
        g_cnt_to[i] = 0; g_cnt_fr[i] = 0; g_selfsum[i] = 0.f;
    }
    if (t < 4) g_loss[t] = 0.f;
}

__global__ void k_count(const int* __restrict__ ei, const float* __restrict__ ea) {
    int e = blockIdx.x * blockDim.x + threadIdx.x;
    if (e >= EE) return;
    int s = ei[e];
    int d = ei[EE + e];
    if (s != d) {
        atomicAdd(&g_cnt_to[d], 1);
        atomicAdd(&g_cnt_fr[s], 1);
    } else {
        atomicAdd(&g_selfsum[s], ea[2 * e]);
    }
}

// ---------------- CSR build: scan + scatter ----------------
__global__ void k_scanA() {
    __shared__ int sh[1024];
    int arr = blockIdx.y;
    int i = blockIdx.x * 1024 + threadIdx.x;
    const int* cnt = arr ? g_cnt_fr : g_cnt_to;
    int* rowp = arr ? g_rowp_fr : g_rowp_to;
    int v = (i < NN) ? cnt[i] : 0;
    sh[threadIdx.x] = v;
    __syncthreads();
#pragma unroll
    for (int off = 1; off < 1024; off <<= 1) {
        int t2 = (threadIdx.x >= off) ? sh[threadIdx.x - off] : 0;
        __syncthreads();
        sh[threadIdx.x] += t2;
        __syncthreads();
    }
    if (i < NN) rowp[i] = sh[threadIdx.x] - v;   // block-local exclusive
    if (threadIdx.x == 1023) g_blks[arr * NB + blockIdx.x] = sh[1023];
}

__global__ void k_scanB() {
    int t = threadIdx.x;
    if (t < 2) {
        int acc = 0;
        for (int b = 0; b < NB; b++) {
            int v = g_blks[t * NB + b];
            g_blks[t * NB + b] = acc;
            acc += v;
        }
        (t ? g_rowp_fr : g_rowp_to)[NN] = acc;
    }
}

__global__ void k_scanC() {
    int arr = blockIdx.y;
    int i = blockIdx.x * 1024 + threadIdx.x;
    if (i >= NN) return;
    int* rowp = arr ? g_rowp_fr : g_rowp_to;
    int* cur  = arr ? g_cur_fr  : g_cur_to;
    int v = rowp[i] + g_blks[arr * NB + blockIdx.x];
    rowp[i] = v;
    cur[i] = v;
}

__global__ void k_scatter(const int* __restrict__ ei, const float* __restrict__ ea) {
    int e = blockIdx.x * blockDim.x + threadIdx.x;
    if (e >= EE) return;
    int s = ei[e];
    int d = ei[EE + e];
    if (s == d) return;
    __half2 eh = __floats2half2_rn(ea[2 * e], ea[2 * e + 1]);
    unsigned ehu = *(unsigned*)&eh;
    u64 hi = ((u64)ehu) << 32;
    int p1 = atomicAdd(&g_cur_to[d], 1);
    g_pay_to[p1] = hi | (unsigned)s;
    int p2 = atomicAdd(&g_cur_fr[s], 1);
    g_pay_fr[p2] = hi | (unsigned)d;
}

// ---------------- weight folding ----------------
__global__ void k_pack(const float* __restrict__ Wih, const float* __restrict__ bih,
                       const float* __restrict__ bhh,
                       const float* __restrict__ toW2, const float* __restrict__ tob2,
                       const float* __restrict__ frW2, const float* __restrict__ frb2,
                       const float* __restrict__ lpW2, const float* __restrict__ lpb2,
                       const float* __restrict__ toW1, const float* __restrict__ tob1,
                       const float* __restrict__ frW1, const float* __restrict__ frb1) {
    int t = blockIdx.x * blockDim.x + threadIdx.x;
    int nt = gridDim.x * blockDim.x;
    for (int idx = t; idx < 96 * 132; idx += nt) {
        int q = idx / 132, c = idx - q * 132;
        float v = 0.f;
        if (c < 32) {
            v = Wih[q * 131 + c];
        } else if (c < 64) {
            int j = c - 32;
            for (int i = 0; i < 32; i++) v += Wih[q * 131 + 32 + i] * toW2[i * 32 + j];
        } else if (c < 96) {
            int j = c - 64;
            for (int i = 0; i < 32; i++) v += Wih[q * 131 + 64 + i] * frW2[i * 32 + j];
        } else if (c < 128) {
            int j = c - 96;
            for (int i = 0; i < 32; i++) v += Wih[q * 131 + 96 + i] * lpW2[i * 32 + j];
        } else if (c < 131) {
            v = Wih[q * 131 + 128 + (c - 128)];
        }
        g_G[idx] = v;
    }
    for (int q = t; q < 96; q += nt) {
        float b = bih[q], ct = 0.f, cf = 0.f;
        for (int i = 0; i < 32; i++) {
            b  += Wih[q * 131 + 96 + i] * lpb2[i];
            ct += Wih[q * 131 + 32 + i] * tob2[i];
            cf += Wih[q * 131 + 64 + i] * frb2[i];
        }
        if (q < 64) b += bhh[q];
        g_bias[q] = b; g_cto[q] = ct; g_cfr[q] = cf;
    }
    for (int i = t; i < 192; i += nt) {
        int r = i >> 5, j = i & 31;
        float v;
        if      (r == 0) v = toW1[j * 66 + 64];
        else if (r == 1) v = toW1[j * 66 + 65];
        else if (r == 2) v = tob1[j];
        else if (r == 3) v = frW1[j * 66 + 64];
        else if (r == 4) v = frW1[j * 66 + 65];
        else             v = frb1[j];
        g_ew[i] = v;
    }
}

// ---------------- edge pass: warp-per-node gather-reduce (no atomics) ----------------
__global__ __launch_bounds__(256) void k_pass() {
    int gwarp = (blockIdx.x * 256 + threadIdx.x) >> 5;
    int lane = threadIdx.x & 31;
    int dir = gwarp >= NN;                 // 0: to (by dst), 1: fr (by src)
    int n = gwarp - dir * NN;
    if (n >= NN) return;

    const int*    rowp = dir ? g_rowp_fr : g_rowp_to;
    const u64*    pay  = dir ? g_pay_fr  : g_pay_to;
    const __half* stat = dir ? g_PsfH    : g_PdtH;
    const __half* gat  = dir ? g_PdfH    : g_PstH;
    float*        outp = dir ? g_sum_fr  : g_sum_to;

    float wa0 = __ldg(&g_ew[dir * 96 + lane]);
    float wa1 = __ldg(&g_ew[dir * 96 + 32 + lane]);
    float bb  = __ldg(&g_ew[dir * 96 + 64 + lane]);

    int beg = __ldg(&rowp[n]);
    int end = __ldg(&rowp[n + 1]);
    float st = __half2float(stat[n * 32 + lane]);
    float base = st + bb;
    float acc = 0.f;
#pragma unroll 4
    for (int e = beg; e < end; e++) {
        u64 p = __ldg(&pay[e]);
        int idx = (int)(unsigned)p;
        unsigned ehu = (unsigned)(p >> 32);
        float2 eaf = __half22float2(*(__half2*)&ehu);
        float g = __half2float(__ldg(&gat[idx * 32 + lane]));
        acc += fmaxf(base + g + eaf.x * wa0 + eaf.y * wa1, 0.f);
    }
    outp[n * 32 + lane] = acc;
}

// ---------------- fused node kernel (f32x2 packed math) ----------------
__global__ __launch_bounds__(128) void k_node(
        const float* __restrict__ x,
        const float* __restrict__ lpW1, const float* __restrict__ lpb1,
        const float* __restrict__ bhh,
        const float* __restrict__ toW1, const float* __restrict__ frW1,
        const float* __restrict__ dec1, const float* __restrict__ decb1,
        const float* __restrict__ dec2, const float* __restrict__ decb2,
        const float* __restrict__ y, float* __restrict__ outF,
        int do_proj, int loss_idx) {
    extern __shared__ float sm[];
    float* sG   = sm;              // 12672
    float* sb   = sG + 12672;      // 96
    float* sct  = sb + 96;         // 96
    float* scf  = sct + 96;        // 96
    float* sbhn = scf + 96;        // 32
    float* sW1f = sbhn + 32;       // 1152 (stride 36)
    float* sb1  = sW1f + 1152;     // 32
    float* sPA  = sb1 + 32;        // 4096
    float* sD1  = sPA + 4096;      // 1024
    float* sD2  = sD1 + 1024;      // 64
    float* sDb1 = sD2 + 64;        // 32
    float* sDb2 = sDb1 + 32;       // 2

    for (int i = threadIdx.x; i < 12672; i += 128) sG[i] = g_G[i];
    for (int i = threadIdx.x; i < 96; i += 128) {
        sb[i] = g_bias[i]; sct[i] = g_cto[i]; scf[i] = g_cfr[i];
    }
    if (threadIdx.x < 32) {
        sbhn[threadIdx.x] = bhh[64 + threadIdx.x];
        sb1[threadIdx.x]  = lpb1[threadIdx.x];
    }
    for (int i = threadIdx.x; i < 32 * 36; i += 128) {
        int tq = i / 36, c = i - tq * 36;
        float v = 0.f;
        if (c < 32)       v = lpW1[tq * 65 + c] + lpW1[tq * 65 + 32 + c];
        else if (c == 32) v = lpW1[tq * 65 + 64];
        sW1f[i] = v;
    }
    for (int i = threadIdx.x; i < 4096; i += 128) {
        int m = i >> 10, r = i & 1023, ii = r >> 5, j = r & 31;
        float v;
        if (m == 0)      v = toW1[ii * 66 + j];        // Pdt
        else if (m == 1) v = frW1[ii * 66 + 32 + j];   // Pdf
        else if (m == 2) v = toW1[ii * 66 + 32 + j];   // Pst
        else             v = frW1[ii * 66 + j];        // Psf
        sPA[i] = v;
    }
    for (int i = threadIdx.x; i < 1024; i += 128) sD1[i] = dec1[i];
    if (threadIdx.x < 64) sD2[threadIdx.x] = dec2[threadIdx.x];
    if (threadIdx.x < 32) sDb1[threadIdx.x] = decb1[threadIdx.x];
    if (threadIdx.x < 2)  sDb2[threadIdx.x] = decb2[threadIdx.x];
    __syncthreads();

    int n = blockIdx.x * 128 + threadIdx.x;
    if (n >= NN) return;

    u64 vHp[16];
#pragma unroll
    for (int k = 0; k < 16; k++)
        vHp[k] = pk(g_H[(2 * k) * NN + n], g_H[(2 * k + 1) * NN + n]);

    int ct = g_cnt_to[n], cf = g_cnt_fr[n];
    float rt = ct > 0 ? 1.f / (float)ct : 0.f;
    float rf = cf > 0 ? 1.f / (float)cf : 0.f;

    u64 vmtp[16], vmfp[16];
#pragma unroll
    for (int j4 = 0; j4 < 8; j4++) {
        float4 a = *(const float4*)&g_sum_to[n * 32 + j4 * 4];
        vmtp[j4 * 2]     = pk(a.x * rt, a.y * rt);
        vmtp[j4 * 2 + 1] = pk(a.z * rt, a.w * rt);
        float4 b = *(const float4*)&g_sum_fr[n * 32 + j4 * 4];
        vmfp[j4 * 2]     = pk(b.x * rf, b.y * rf);
        vmfp[j4 * 2 + 1] = pk(b.z * rf, b.w * rf);
    }

    float lc = -g_selfsum[n];   // loop_col = 1 - diag = -selfsum
    u64 vt1p[16];
#pragma unroll
    for (int i2 = 0; i2 < 16; i2++) {
        int i0 = 2 * i2;
        u64 acc0 = pk(sb1[i0]     + sW1f[i0 * 36 + 32] * lc, 0.f);
        u64 acc1 = pk(sb1[i0 + 1] + sW1f[(i0 + 1) * 36 + 32] * lc, 0.f);
#pragma unroll
        for (int j4 = 0; j4 < 8; j4++) {
            ulonglong2 w0 = *(const ulonglong2*)&sW1f[i0 * 36 + j4 * 4];
            ulonglong2 w1 = *(const ulonglong2*)&sW1f[(i0 + 1) * 36 + j4 * 4];
            ffma2(acc0, w0.x, vHp[j4 * 2]); ffma2(acc0, w0.y, vHp[j4 * 2 + 1]);
            ffma2(acc1, w1.x, vHp[j4 * 2]); ffma2(acc1, w1.y, vHp[j4 * 2 + 1]);
        }
        float a0, b0, a1, b1;
        upk(acc0, a0, b0); upk(acc1, a1, b1);
        vt1p[i2] = pk(fmaxf(a0 + b0, 0.f), fmaxf(a1 + b1, 0.f));
    }

    float x0 = x[n * 3], x1 = x[n * 3 + 1], x2 = x[n * 3 + 2];
    u64 xlo = pk(x0, x1), xhi = pk(x2, 0.f);

    for (int qc = 0; qc < 16; qc++) {
        int q0 = qc * 2;
        float bR0 = sb[q0],      bR1 = sb[q0 + 1];
        float bZ0 = sb[32 + q0], bZ1 = sb[33 + q0];
        float bN0 = sb[64 + q0], bN1 = sb[65 + q0];
        if (ct > 0) {
            bR0 += sct[q0]; bR1 += sct[q0 + 1];
            bZ0 += sct[32 + q0]; bZ1 += sct[33 + q0];
            bN0 += sct[64 + q0]; bN1 += sct[65 + q0];
        }
        if (cf > 0) {
            bR0 += scf[q0]; bR1 += scf[q0 + 1];
            bZ0 += scf[32 + q0]; bZ1 += scf[33 + q0];
            bN0 += scf[64 + q0]; bN1 += scf[65 + q0];
        }
        u64 AR0 = pk(bR0, 0.f), AR1 = pk(bR1, 0.f);
        u64 AZ0 = pk(bZ0, 0.f), AZ1 = pk(bZ1, 0.f);
        u64 AN0 = pk(bN0, 0.f), AN1 = pk(bN1, 0.f);
#pragma unroll
        for (int j4 = 0; j4 < 33; j4++) {
            u64 vlo, vhi;
            if (j4 < 8)       { vlo = vHp[j4 * 2];          vhi = vHp[j4 * 2 + 1]; }
            else if (j4 < 16) { vlo = vmtp[(j4 - 8) * 2];   vhi = vmtp[(j4 - 8) * 2 + 1]; }
            else if (j4 < 24) { vlo = vmfp[(j4 - 16) * 2];  vhi = vmfp[(j4 - 16) * 2 + 1]; }
            else if (j4 < 32) { vlo = vt1p[(j4 - 24) * 2];  vhi = vt1p[(j4 - 24) * 2 + 1]; }
            else              { vlo = xlo; vhi = xhi; }
            ulonglong2 w;
            w = *(const ulonglong2*)&sG[(q0)      * 132 + j4 * 4]; ffma2(AR0, w.x, vlo); ffma2(AR0, w.y, vhi);
            w = *(const ulonglong2*)&sG[(q0 + 1)  * 132 + j4 * 4]; ffma2(AR1, w.x, vlo); ffma2(AR1, w.y, vhi);
            w = *(const ulonglong2*)&sG[(32 + q0) * 132 + j4 * 4]; ffma2(AZ0, w.x, vlo); ffma2(AZ0, w.y, vhi);
            w = *(const ulonglong2*)&sG[(33 + q0) * 132 + j4 * 4]; ffma2(AZ1, w.x, vlo); ffma2(AZ1, w.y, vhi);
            w = *(const ulonglong2*)&sG[(64 + q0) * 132 + j4 * 4]; ffma2(AN0, w.x, vlo); ffma2(AN0, w.y, vhi);
            w = *(const ulonglong2*)&sG[(65 + q0) * 132 + j4 * 4]; ffma2(AN1, w.x, vlo); ffma2(AN1, w.y, vhi);
        }
#pragma unroll
        for (int i = 0; i < 2; i++) {
            int q = q0 + i;
            float lo, hi;
            upk(i ? AR1 : AR0, lo, hi); float aR = lo + hi;
            upk(i ? AZ1 : AZ0, lo, hi); float aZ = lo + hi;
            upk(i ? AN1 : AN0, lo, hi); float aN = lo + hi;
            float r = 1.f / (1.f + __expf(-aR));
            float z = 1.f / (1.f + __expf(-aZ));
            float tn = aN + r * sbhn[q];
            float th = 2.f / (1.f + __expf(-2.f * tn)) - 1.f;
            float gru = (1.f - z) * th;
            int off = q * NN + n;
            g_H[off] = g_H[off] + 0.5f * gru;    // ALPHA = 0.5
        }
    }

    // reload updated H (L2-hot)
#pragma unroll
    for (int k = 0; k < 16; k++)
        vHp[k] = pk(g_H[(2 * k) * NN + n], g_H[(2 * k + 1) * NN + n]);

    if (do_proj) {
        for (int i4 = 0; i4 < 8; i4++) {
            u64 A[16];
#pragma unroll
            for (int t = 0; t < 16; t++) A[t] = 0ull;
#pragma unroll
            for (int j4 = 0; j4 < 8; j4++) {
                u64 vlo = vHp[j4 * 2], vhi = vHp[j4 * 2 + 1];
#pragma unroll
                for (int m = 0; m < 4; m++) {
#pragma unroll
                    for (int ii = 0; ii < 4; ii++) {
                        ulonglong2 w = *(const ulonglong2*)&sPA[m * 1024 + (i4 * 4 + ii) * 32 + j4 * 4];
                        ffma2(A[m * 4 + ii], w.x, vlo);
                        ffma2(A[m * 4 + ii], w.y, vhi);
                    }
                }
            }
            float v[16];
#pragma unroll
            for (int t = 0; t < 16; t++) {
                float lo, hi; upk(A[t], lo, hi);
                v[t] = lo + hi;
            }
            __half2 h01, h23;
            uint2 st;
            h01 = __floats2half2_rn(v[0], v[1]);  h23 = __floats2half2_rn(v[2], v[3]);
            st.x = *(unsigned*)&h01; st.y = *(unsigned*)&h23;
            *(uint2*)&g_PdtH[n * 32 + i4 * 4] = st;
            h01 = __floats2half2_rn(v[4], v[5]);  h23 = __floats2half2_rn(v[6], v[7]);
            st.x = *(unsigned*)&h01; st.y = *(unsigned*)&h23;
            *(uint2*)&g_PdfH[n * 32 + i4 * 4] = st;
            h01 = __floats2half2_rn(v[8], v[9]);  h23 = __floats2half2_rn(v[10], v[11]);
            st.x = *(unsigned*)&h01; st.y = *(unsigned*)&h23;
            *(uint2*)&g_PstH[n * 32 + i4 * 4] = st;
            h01 = __floats2half2_rn(v[12], v[13]); h23 = __floats2half2_rn(v[14], v[15]);
            st.x = *(unsigned*)&h01; st.y = *(unsigned*)&h23;
            *(uint2*)&g_PsfH[n * 32 + i4 * 4] = st;
        }
    }

    // decode + loss
    {
        float F0 = sDb2[0], F1 = sDb2[1];
        for (int i = 0; i < 32; i++) {
            u64 acc = pk(sDb1[i], 0.f);
#pragma unroll
            for (int j4 = 0; j4 < 8; j4++) {
                ulonglong2 w = *(const ulonglong2*)&sD1[i * 32 + j4 * 4];
                ffma2(acc, w.x, vHp[j4 * 2]);
                ffma2(acc, w.y, vHp[j4 * 2 + 1]);
            }
            float lo, hi; upk(acc, lo, hi);
            float a = fmaxf(lo + hi, 0.f);
            F0 += sD2[i] * a;
            F1 += sD2[32 + i] * a;
        }
        float d0 = F0 - y[n * 2], d1 = F1 - y[n * 2 + 1];
        float sse = d0 * d0 + d1 * d1;
        if (outF) { outF[n * 2] = F0; outF[n * 2 + 1] = F1; }
#pragma unroll
        for (int o = 16; o; o >>= 1) sse += __shfl_down_sync(0xffffffffu, sse, o);
        if ((threadIdx.x & 31) == 0) atomicAdd(&g_loss[loss_idx], sse);
    }
}

// ---------------- finalize losses ----------------
__global__ void k_final(float* __restrict__ out) {
    if (blockIdx.x == 0 && threadIdx.x == 0) {
        float inv = 1.f / (2.f * (float)NN);
        float l0 = g_loss[0] * inv;
        float l1 = g_loss[1] * inv;
        float l2 = g_loss[2] * inv;
        float l3 = g_loss[3] * inv;
        out[200000] = 0.729f * l0 + 0.81f * l1 + 0.9f * l2 + l3;
        out[200001] = l0; out[200002] = l1; out[200003] = l2; out[200004] = l3;
    }
}

// ---------------- launch ----------------
extern "C" void kernel_launch(void* const* d_in, const int* in_sizes, int n_in,
                              void* d_out, int out_size) {
    const float* x    = (const float*)d_in[0];
    const float* y    = (const float*)d_in[1];
    const int*   ei   = (const int*)d_in[2];
    const float* ea   = (const float*)d_in[3];
    const float* toW1 = (const float*)d_in[4];
    const float* tob1 = (const float*)d_in[5];
    const float* toW2 = (const float*)d_in[6];
    const float* tob2 = (const float*)d_in[7];
    const float* frW1 = (const float*)d_in[8];
    const float* frb1 = (const float*)d_in[9];
    const float* frW2 = (const float*)d_in[10];
    const float* frb2 = (const float*)d_in[11];
    const float* lpW1 = (const float*)d_in[12];
    const float* lpb1 = (const float*)d_in[13];
    const float* lpW2 = (const float*)d_in[14];
    const float* lpb2 = (const float*)d_in[15];
    const float* Wih  = (const float*)d_in[16];
    const float* bih  = (const float*)d_in[17];
    // d_in[18] = gru_Whh (unused: h0 = 0)
    const float* bhh  = (const float*)d_in[19];
    const float* dec1 = (const float*)d_in[20];
    const float* decb1= (const float*)d_in[21];
    const float* dec2 = (const float*)d_in[22];
    const float* decb2= (const float*)d_in[23];
    float* out = (float*)d_out;

    const int node_smem = 19394 * 4;   // 77576 bytes
    cudaFuncSetAttribute(k_node, cudaFuncAttributeMaxDynamicSharedMemorySize, node_smem);

    k_init<<<1024, 256>>>();
    k_count<<<(EE + 255) / 256, 256>>>(ei, ea);
    k_pack<<<8, 256>>>(Wih, bih, bhh, toW2, tob2, frW2, frb2, lpW2, lpb2,
                       toW1, tob1, frW1, frb1);
    dim3 sgrid(NB, 2);
    k_scanA<<<sgrid, 1024>>>();
    k_scanB<<<1, 32>>>();
    k_scanC<<<sgrid, 1024>>>();
    k_scatter<<<(EE + 255) / 256, 256>>>(ei, ea);

    int nblk = (NN + 127) / 128;
    for (int step = 0; step < 4; step++) {
        k_pass<<<(2 * NN + 7) / 8, 256>>>();
        k_node<<<nblk, 128, node_smem>>>(x, lpW1, lpb1, bhh, toW1, frW1,
                                         dec1, decb1, dec2, decb2, y,
                                         (step == 3) ? out : nullptr,
                                         (step < 3) ? 1 : 0, step);
    }
    k_final<<<1, 32>>>(out);
}

// round 8
// speedup vs baseline: 2.1420x; 1.0300x over previous
#include <cuda_runtime.h>
#include <cuda_fp16.h>
#include <math.h>

#define NN 100000
#define EE 3200000
#define NB 98   // ceil(NN/1024)

typedef unsigned long long u64;

__device__ __forceinline__ u64 pk(float a, float b) {
    u64 r; asm("mov.b64 %0,{%1,%2};" : "=l"(r) : "f"(a), "f"(b)); return r;
}
__device__ __forceinline__ void upk(u64 v, float& a, float& b) {
    asm("mov.b64 {%0,%1},%2;" : "=f"(a), "=f"(b) : "l"(v));
}
__device__ __forceinline__ void ffma2(u64& d, u64 a, u64 b) {
    asm("fma.rn.f32x2 %0,%1,%2,%0;" : "+l"(d) : "l"(a), "l"(b));
}

// ---------------- device scratch ----------------
__device__ __align__(16) float  g_H[32 * NN];       // [q][n]
__device__ __align__(16) __half g_PdtH[NN * 32];
__device__ __align__(16) __half g_PdfH[NN * 32];
__device__ __align__(16) __half g_PstH[NN * 32];
__device__ __align__(16) __half g_PsfH[NN * 32];
__device__ __align__(16) float g_sum_to[NN * 32];
__device__ __align__(16) float g_sum_fr[NN * 32];
__device__ __align__(16) u64   g_C[66 * NN];        // concat vector, paired, [j2][n]
__device__ int   g_cnt_to[NN];
__device__ int   g_cnt_fr[NN];
__device__ float g_selfsum[NN];
__device__ float g_loss[4];

// CSR
__device__ int g_rowp_to[NN + 1];
__device__ int g_rowp_fr[NN + 1];
__device__ int g_cur_to[NN];
__device__ int g_cur_fr[NN];
__device__ u64 g_pay_to[EE];
__device__ u64 g_pay_fr[EE];
__device__ int g_blks[2 * NB];

// packed/folded weights
__device__ __align__(16) float g_G[96 * 132];       // [q][c] folded GRU matrix
__device__ __align__(16) u64   g_Gp[132 * 48];      // [j][qp] = (G[2qp][j], G[2qp+1][j])
__device__ float g_bias[96];
__device__ float g_cto[96];
__device__ float g_cfr[96];
__device__ __align__(16) float g_ew[192];

// ---------------- init ----------------
__global__ void k_init() {
    int t = blockIdx.x * blockDim.x + threadIdx.x;
    int nt = gridDim.x * blockDim.x;
    __half hz = __float2half(0.f);
    for (int i = t; i < 32 * NN; i += nt) {
        g_H[i] = 0.f;
        g_PdtH[i] = hz; g_PdfH[i] = hz; g_PstH[i] = hz; g_PsfH[i] = hz;
    }
    for (int i = t; i < NN; i += nt) {
        g_cnt_to[i] = 0; g_cnt_fr[i] = 0; g_selfsum[i] = 0.f;
    }
    if (t < 4) g_loss[t] = 0.f;
}

__global__ void k_count(const int* __restrict__ ei, const float* __restrict__ ea) {
    int e = blockIdx.x * blockDim.x + threadIdx.x;
    if (e >= EE) return;
    int s = ei[e];
    int d = ei[EE + e];
    if (s != d) {
        atomicAdd(&g_cnt_to[d], 1);
        atomicAdd(&g_cnt_fr[s], 1);
    } else {
        atomicAdd(&g_selfsum[s], ea[2 * e]);
    }
}

// ---------------- CSR build ----------------
__global__ void k_scanA() {
    __shared__ int sh[1024];
    int arr = blockIdx.y;
    int i = blockIdx.x * 1024 + threadIdx.x;
    const int* cnt = arr ? g_cnt_fr : g_cnt_to;
    int* rowp = arr ? g_rowp_fr : g_rowp_to;
    int v = (i < NN) ? cnt[i] : 0;
    sh[threadIdx.x] = v;
    __syncthreads();
#pragma unroll
    for (int off = 1; off < 1024; off <<= 1) {
        int t2 = (threadIdx.x >= off) ? sh[threadIdx.x - off] : 0;
        __syncthreads();
        sh[threadIdx.x] += t2;
        __syncthreads();
    }
    if (i < NN) rowp[i] = sh[threadIdx.x] - v;
    if (threadIdx.x == 1023) g_blks[arr * NB + blockIdx.x] = sh[1023];
}

__global__ void k_scanB() {
    int t = threadIdx.x;
    if (t < 2) {
        int acc = 0;
        for (int b = 0; b < NB; b++) {
            int v = g_blks[t * NB + b];
            g_blks[t * NB + b] = acc;
            acc += v;
        }
        (t ? g_rowp_fr : g_rowp_to)[NN] = acc;
    }
}

__global__ void k_scanC() {
    int arr = blockIdx.y;
    int i = blockIdx.x * 1024 + threadIdx.x;
    if (i >= NN) return;
    int* rowp = arr ? g_rowp_fr : g_rowp_to;
    int* cur  = arr ? g_cur_fr  : g_cur_to;
    int v = rowp[i] + g_blks[arr * NB + blockIdx.x];
    rowp[i] = v;
    cur[i] = v;
}

__global__ void k_scatter(const int* __restrict__ ei, const float* __restrict__ ea) {
    int e = blockIdx.x * blockDim.x + threadIdx.x;
    if (e >= EE) return;
    int s = ei[e];
    int d = ei[EE + e];
    if (s == d) return;
    __half2 eh = __floats2half2_rn(ea[2 * e], ea[2 * e + 1]);
    unsigned ehu = *(unsigned*)&eh;
    u64 hi = ((u64)ehu) << 32;
    int p1 = atomicAdd(&g_cur_to[d], 1);
    g_pay_to[p1] = hi | (unsigned)s;
    int p2 = atomicAdd(&g_cur_fr[s], 1);
    g_pay_fr[p2] = hi | (unsigned)d;
}

// ---------------- weight folding ----------------
__global__ void k_pack(const float* __restrict__ Wih, const float* __restrict__ bih,
                       const float* __restrict__ bhh,
                       const float* __restrict__ toW2, const float* __restrict__ tob2,
                       const float* __restrict__ frW2, const float* __restrict__ frb2,
                       const float* __restrict__ lpW2, const float* __restrict__ lpb2,
                       const float* __restrict__ toW1, const float* __restrict__ tob1,
                       const float* __restrict__ frW1, const float* __restrict__ frb1) {
    int t = blockIdx.x * blockDim.x + threadIdx.x;
    int nt = gridDim.x * blockDim.x;
    for (int idx = t; idx < 96 * 132; idx += nt) {
        int q = idx / 132, c = idx - q * 132;
        float v = 0.f;
        if (c < 32) {
            v = Wih[q * 131 + c];
        } else if (c < 64) {
            int j = c - 32;
            for (int i = 0; i < 32; i++) v += Wih[q * 131 + 32 + i] * toW2[i * 32 + j];
        } else if (c < 96) {
            int j = c - 64;
            for (int i = 0; i < 32; i++) v += Wih[q * 131 + 64 + i] * frW2[i * 32 + j];
        } else if (c < 128) {
            int j = c - 96;
            for (int i = 0; i < 32; i++) v += Wih[q * 131 + 96 + i] * lpW2[i * 32 + j];
        } else if (c < 131) {
            v = Wih[q * 131 + 128 + (c - 128)];
        }
        g_G[idx] = v;
    }
    for (int q = t; q < 96; q += nt) {
        float b = bih[q], ct = 0.f, cf = 0.f;
        for (int i = 0; i < 32; i++) {
            b  += Wih[q * 131 + 96 + i] * lpb2[i];
            ct += Wih[q * 131 + 32 + i] * tob2[i];
            cf += Wih[q * 131 + 64 + i] * frb2[i];
        }
        if (q < 64) b += bhh[q];
        g_bias[q] = b; g_cto[q] = ct; g_cfr[q] = cf;
    }
    for (int i = t; i < 192; i += nt) {
        int r = i >> 5, j = i & 31;
        float v;
        if      (r == 0) v = toW1[j * 66 + 64];
        else if (r == 1) v = toW1[j * 66 + 65];
        else if (r == 2) v = tob1[j];
        else if (r == 3) v = frW1[j * 66 + 64];
        else if (r == 4) v = frW1[j * 66 + 65];
        else             v = frb1[j];
        g_ew[i] = v;
    }
}

__global__ void k_pack2() {
    int t = blockIdx.x * blockDim.x + threadIdx.x;
    int nt = gridDim.x * blockDim.x;
    for (int idx = t; idx < 132 * 48; idx += nt) {
        int j = idx / 48, qp = idx - j * 48;
        g_Gp[idx] = pk(g_G[(2 * qp) * 132 + j], g_G[(2 * qp + 1) * 132 + j]);
    }
}

// ---------------- edge pass: warp-per-node gather-reduce ----------------
__global__ __launch_bounds__(256) void k_pass() {
    int gwarp = (blockIdx.x * 256 + threadIdx.x) >> 5;
    int lane = threadIdx.x & 31;
    int dir = gwarp >= NN;
    int n = gwarp - dir * NN;
    if (n >= NN) return;

    const int*    rowp = dir ? g_rowp_fr : g_rowp_to;
    const u64*    pay  = dir ? g_pay_fr  : g_pay_to;
    const __half* stat = dir ? g_PsfH    : g_PdtH;
    const __half* gat  = dir ? g_PdfH    : g_PstH;
    float*        outp = dir ? g_sum_fr  : g_sum_to;

    float wa0 = __ldg(&g_ew[dir * 96 + lane]);
    float wa1 = __ldg(&g_ew[dir * 96 + 32 + lane]);
    float bb  = __ldg(&g_ew[dir * 96 + 64 + lane]);

    int beg = __ldg(&rowp[n]);
    int end = __ldg(&rowp[n + 1]);
    float st = __half2float(stat[n * 32 + lane]);
    float base = st + bb;
    float acc = 0.f;
#pragma unroll 4
    for (int e = beg; e < end; e++) {
        u64 p = __ldg(&pay[e]);
        int idx = (int)(unsigned)p;
        unsigned ehu = (unsigned)(p >> 32);
        float2 eaf = __half22float2(*(__half2*)&ehu);
        float g = __half2float(__ldg(&gat[idx * 32 + lane]));
        acc += fmaxf(base + g + eaf.x * wa0 + eaf.y * wa1, 0.f);
    }
    outp[n * 32 + lane] = acc;
}

// ---------------- k_prep: build concat vector C [66][NN] (paired f32) ----------------
__global__ __launch_bounds__(128) void k_prep(const float* __restrict__ x,
                                              const float* __restrict__ lpW1,
                                              const float* __restrict__ lpb1) {
    __shared__ float sW1f[1152];   // stride 36
    __shared__ float sb1[32];
    for (int i = threadIdx.x; i < 1152; i += 128) {
        int tq = i / 36, c = i - tq * 36;
        float v = 0.f;
        if (c < 32)       v = lpW1[tq * 65 + c] + lpW1[tq * 65 + 32 + c];
        else if (c == 32) v = lpW1[tq * 65 + 64];
        sW1f[i] = v;
    }
    if (threadIdx.x < 32) sb1[threadIdx.x] = lpb1[threadIdx.x];
    __syncthreads();

    int n = blockIdx.x * 128 + threadIdx.x;
    if (n >= NN) return;

    u64 vHp[16];
#pragma unroll
    for (int k = 0; k < 16; k++) {
        vHp[k] = pk(g_H[(2 * k) * NN + n], g_H[(2 * k + 1) * NN + n]);
        g_C[k * NN + n] = vHp[k];
    }

    int ct = g_cnt_to[n], cf = g_cnt_fr[n];
    float rt = ct > 0 ? 1.f / (float)ct : 0.f;
    float rf = cf > 0 ? 1.f / (float)cf : 0.f;
#pragma unroll
    for (int j4 = 0; j4 < 8; j4++) {
        float4 a = *(const float4*)&g_sum_to[n * 32 + j4 * 4];
        g_C[(16 + j4 * 2) * NN + n] = pk(a.x * rt, a.y * rt);
        g_C[(17 + j4 * 2) * NN + n] = pk(a.z * rt, a.w * rt);
        float4 b = *(const float4*)&g_sum_fr[n * 32 + j4 * 4];
        g_C[(32 + j4 * 2) * NN + n] = pk(b.x * rf, b.y * rf);
        g_C[(33 + j4 * 2) * NN + n] = pk(b.z * rf, b.w * rf);
    }

    float lc = -g_selfsum[n];   // loop_col = 1 - diag
#pragma unroll
    for (int i2 = 0; i2 < 16; i2++) {
        int i0 = 2 * i2;
        u64 acc0 = pk(sb1[i0]     + sW1f[i0 * 36 + 32] * lc, 0.f);
        u64 acc1 = pk(sb1[i0 + 1] + sW1f[(i0 + 1) * 36 + 32] * lc, 0.f);
#pragma unroll
        for (int j4 = 0; j4 < 8; j4++) {
            ulonglong2 w0 = *(const ulonglong2*)&sW1f[i0 * 36 + j4 * 4];
            ulonglong2 w1 = *(const ulonglong2*)&sW1f[(i0 + 1) * 36 + j4 * 4];
            ffma2(acc0, w0.x, vHp[j4 * 2]); ffma2(acc0, w0.y, vHp[j4 * 2 + 1]);
            ffma2(acc1, w1.x, vHp[j4 * 2]); ffma2(acc1, w1.y, vHp[j4 * 2 + 1]);
        }
        float a0, b0, a1, b1;
        upk(acc0, a0, b0); upk(acc1, a1, b1);
        g_C[(48 + i2) * NN + n] = pk(fmaxf(a0 + b0, 0.f), fmaxf(a1 + b1, 0.f));
    }

    float x0 = x[n * 3], x1 = x[n * 3 + 1], x2 = x[n * 3 + 2];
    g_C[64 * NN + n] = pk(x0, x1);
    g_C[65 * NN + n] = pk(x2, 0.f);
}

// ---------------- k_gru: output-stationary GEMV, streamed inputs ----------------
__global__ __launch_bounds__(128, 3) void k_gru(const float* __restrict__ bhh) {
    extern __shared__ u64 smu[];
    u64*   sGp  = smu;                       // 6336 u64
    float* sb   = (float*)(smu + 6336);      // 96
    float* sct  = sb + 96;                   // 96
    float* scf  = sct + 96;                  // 96
    float* sbhn = scf + 96;                  // 32

    for (int i = threadIdx.x; i < 6336; i += 128) sGp[i] = g_Gp[i];
    for (int i = threadIdx.x; i < 96; i += 128) {
        sb[i] = g_bias[i]; sct[i] = g_cto[i]; scf[i] = g_cfr[i];
    }
    if (threadIdx.x < 32) sbhn[threadIdx.x] = bhh[64 + threadIdx.x];
    __syncthreads();

    int n = blockIdx.x * 128 + threadIdx.x;
    if (n >= NN) return;

    float ft = (__ldg(&g_cnt_to[n]) > 0) ? 1.f : 0.f;
    float ff = (__ldg(&g_cnt_fr[n]) > 0) ? 1.f : 0.f;

    u64 acc[48];
#pragma unroll
    for (int qp = 0; qp < 48; qp++) {
        int q0 = 2 * qp, q1 = q0 + 1;
        acc[qp] = pk(sb[q0] + ft * sct[q0] + ff * scf[q0],
                     sb[q1] + ft * sct[q1] + ff * scf[q1]);
    }

#pragma unroll 2
    for (int j2 = 0; j2 < 66; j2++) {
        u64 c = __ldg(&g_C[j2 * NN + n]);
        float v0, v1; upk(c, v0, v1);
        u64 s0 = pk(v0, v0), s1 = pk(v1, v1);
        const u64* w0p = &sGp[(2 * j2) * 48];
        const u64* w1p = &sGp[(2 * j2 + 1) * 48];
#pragma unroll
        for (int qb = 0; qb < 24; qb++) {
            ulonglong2 w = *(const ulonglong2*)&w0p[qb * 2];
            ffma2(acc[qb * 2], w.x, s0);
            ffma2(acc[qb * 2 + 1], w.y, s0);
        }
#pragma unroll
        for (int qb = 0; qb < 24; qb++) {
            ulonglong2 w = *(const ulonglong2*)&w1p[qb * 2];
            ffma2(acc[qb * 2], w.x, s1);
            ffma2(acc[qb * 2 + 1], w.y, s1);
        }
    }

#pragma unroll
    for (int i = 0; i < 16; i++) {
        float aR0, aR1, aZ0, aZ1, aN0, aN1;
        upk(acc[i], aR0, aR1);
        upk(acc[16 + i], aZ0, aZ1);
        upk(acc[32 + i], aN0, aN1);
        int q0 = 2 * i, q1 = q0 + 1;
        float r0 = 1.f / (1.f + __expf(-aR0));
        float r1 = 1.f / (1.f + __expf(-aR1));
        float z0 = 1.f / (1.f + __expf(-aZ0));
        float z1 = 1.f / (1.f + __expf(-aZ1));
        float tn0 = aN0 + r0 * sbhn[q0];
        float tn1 = aN1 + r1 * sbhn[q1];
        float th0 = 2.f / (1.f + __expf(-2.f * tn0)) - 1.f;
        float th1 = 2.f / (1.f + __expf(-2.f * tn1)) - 1.f;
        g_H[q0 * NN + n] += 0.5f * (1.f - z0) * th0;   // ALPHA = 0.5
        g_H[q1 * NN + n] += 0.5f * (1.f - z1) * th1;
    }
}

// ---------------- k_post: proj (split by blockIdx.y) + decode + loss ----------------
__global__ __launch_bounds__(128) void k_post(
        const float* __restrict__ toW1, const float* __restrict__ frW1,
        const float* __restrict__ dec1, const float* __restrict__ decb1,
        const float* __restrict__ dec2, const float* __restrict__ decb2,
        const float* __restrict__ y, float* __restrict__ outF,
        int do_proj, int loss_idx) {
    __shared__ float sPA[2048];    // this half's two matrices
    __shared__ float sD1[1024];
    __shared__ float sD2[64];
    __shared__ float sDb1[32];
    __shared__ float sDb2[2];

    int half = blockIdx.y;
    if (do_proj) {
        for (int i = threadIdx.x; i < 2048; i += 128) {
            int m = half * 2 + (i >> 10), r = i & 1023, ii = r >> 5, j = r & 31;
            float v;
            if (m == 0)      v = toW1[ii * 66 + j];        // Pdt
            else if (m == 1) v = frW1[ii * 66 + 32 + j];   // Pdf
            else if (m == 2) v = toW1[ii * 66 + 32 + j];   // Pst
            else             v = frW1[ii * 66 + j];        // Psf
            sPA[i] = v;
        }
    }
    if (half == 0) {
        for (int i = threadIdx.x; i < 1024; i += 128) sD1[i] = dec1[i];
        if (threadIdx.x < 64) sD2[threadIdx.x] = dec2[threadIdx.x];
        if (threadIdx.x < 32) sDb1[threadIdx.x] = decb1[threadIdx.x];
        if (threadIdx.x < 2)  sDb2[threadIdx.x] = decb2[threadIdx.x];
    }
    __syncthreads();

    int n = blockIdx.x * 128 + threadIdx.x;
    if (n >= NN) return;

    u64 vHp[16];
#pragma unroll
    for (int k = 0; k < 16; k++)
        vHp[k] = pk(g_H[(2 * k) * NN + n], g_H[(2 * k + 1) * NN + n]);

    if (do_proj) {
        __half* outA = half ? g_PstH : g_PdtH;
        __half* outB = half ? g_PsfH : g_PdfH;
        for (int i4 = 0; i4 < 8; i4++) {
            u64 A[8];
#pragma unroll
            for (int t = 0; t < 8; t++) A[t] = 0ull;
#pragma unroll
            for (int j4 = 0; j4 < 8; j4++) {
                u64 vlo = vHp[j4 * 2], vhi = vHp[j4 * 2 + 1];
#pragma unroll
                for (int mm = 0; mm < 2; mm++) {
#pragma unroll
                    for (int ii = 0; ii < 4; ii++) {
                        ulonglong2 w = *(const ulonglong2*)&sPA[mm * 1024 + (i4 * 4 + ii) * 32 + j4 * 4];
                        ffma2(A[mm * 4 + ii], w.x, vlo);
                        ffma2(A[mm * 4 + ii], w.y, vhi);
                    }
                }
            }
            __half2 hA01, hA23, hB01, hB23;
            float l0, h0, l1, h1, l2, h2, l3, h3;
            upk(A[0], l0, h0); upk(A[1], l1, h1); upk(A[2], l2, h2); upk(A[3], l3, h3);
            hA01 = __floats2half2_rn(l0 + h0, l1 + h1);
            hA23 = __floats2half2_rn(l2 + h2, l3 + h3);
            upk(A[4], l0, h0); upk(A[5], l1, h1); upk(A[6], l2, h2); upk(A[7], l3, h3);
            hB01 = __floats2half2_rn(l0 + h0, l1 + h1);
            hB23 = __floats2half2_rn(l2 + h2, l3 + h3);
            uint2 stA, stB;
            stA.x = *(unsigned*)&hA01; stA.y = *(unsigned*)&hA23;
            stB.x = *(unsigned*)&hB01; stB.y = *(unsigned*)&hB23;
            *(uint2*)&outA[n * 32 + i4 * 4] = stA;
            *(uint2*)&outB[n * 32 + i4 * 4] = stB;
        }
    }

    if (half == 0) {
        float F0 = sDb2[0], F1 = sDb2[1];
        for (int i = 0; i < 32; i++) {
            u64 acc = pk(sDb1[i], 0.f);
#pragma unroll
            for (int j4 = 0; j4 < 8; j4++) {
                ulonglong2 w = *(const ulonglong2*)&sD1[i * 32 + j4 * 4];
                ffma2(acc, w.x, vHp[j4 * 2]);
                ffma2(acc, w.y, vHp[j4 * 2 + 1]);
            }
            float lo, hi; upk(acc, lo, hi);
            float a = fmaxf(lo + hi, 0.f);
            F0 += sD2[i] * a;
            F1 += sD2[32 + i] * a;
        }
        float d0 = F0 - y[n * 2], d1 = F1 - y[n * 2 + 1];
        float sse = d0 * d0 + d1 * d1;
        if (outF) { outF[n * 2] = F0; outF[n * 2 + 1] = F1; }
#pragma unroll
        for (int o = 16; o; o >>= 1) sse += __shfl_down_sync(0xffffffffu, sse, o);
        if ((threadIdx.x & 31) == 0) atomicAdd(&g_loss[loss_idx], sse);
    }
}

// ---------------- finalize losses ----------------
__global__ void k_final(float* __restrict__ out) {
    if (blockIdx.x == 0 && threadIdx.x == 0) {
        float inv = 1.f / (2.f * (float)NN);
        float l0 = g_loss[0] * inv;
        float l1 = g_loss[1] * inv;
        float l2 = g_loss[2] * inv;
        float l3 = g_loss[3] * inv;
        out[200000] = 0.729f * l0 + 0.81f * l1 + 0.9f * l2 + l3;
        out[200001] = l0; out[200002] = l1; out[200003] = l2; out[200004] = l3;
    }
}

// ---------------- launch ----------------
extern "C" void kernel_launch(void* const* d_in, const int* in_sizes, int n_in,
                              void* d_out, int out_size) {
    const float* x    = (const float*)d_in[0];
    const float* y    = (const float*)d_in[1];
    const int*   ei   = (const int*)d_in[2];
    const float* ea   = (const float*)d_in[3];
    const float* toW1 = (const float*)d_in[4];
    const float* tob1 = (const float*)d_in[5];
    const float* toW2 = (const float*)d_in[6];
    const float* tob2 = (const float*)d_in[7];
    const float* frW1 = (const float*)d_in[8];
    const float* frb1 = (const float*)d_in[9];
    const float* frW2 = (const float*)d_in[10];
    const float* frb2 = (const float*)d_in[11];
    const float* lpW1 = (const float*)d_in[12];
    const float* lpb1 = (const float*)d_in[13];
    const float* lpW2 = (const float*)d_in[14];
    const float* lpb2 = (const float*)d_in[15];
    const float* Wih  = (const float*)d_in[16];
    const float* bih  = (const float*)d_in[17];
    // d_in[18] = gru_Whh (unused: h0 = 0)
    const float* bhh  = (const float*)d_in[19];
    const float* dec1 = (const float*)d_in[20];
    const float* decb1= (const float*)d_in[21];
    const float* dec2 = (const float*)d_in[22];
    const float* decb2= (const float*)d_in[23];
    float* out = (float*)d_out;

    const int gru_smem = 6336 * 8 + 320 * 4;   // 51968 bytes
    cudaFuncSetAttribute(k_gru, cudaFuncAttributeMaxDynamicSharedMemorySize, gru_smem);

    k_init<<<1024, 256>>>();
    k_count<<<(EE + 255) / 256, 256>>>(ei, ea);
    k_pack<<<8, 256>>>(Wih, bih, bhh, toW2, tob2, frW2, frb2, lpW2, lpb2,
                       toW1, tob1, frW1, frb1);
    k_pack2<<<8, 256>>>();
    dim3 sgrid(NB, 2);
    k_scanA<<<sgrid, 1024>>>();
    k_scanB<<<1, 32>>>();
    k_scanC<<<sgrid, 1024>>>();
    k_scatter<<<(EE + 255) / 256, 256>>>(ei, ea);

    int nblk = (NN + 127) / 128;
    for (int step = 0; step < 4; step++) {
        int do_proj = (step < 3) ? 1 : 0;
        k_pass<<<(2 * NN + 7) / 8, 256>>>();
        k_prep<<<nblk, 128>>>(x, lpW1, lpb1);
        k_gru<<<nblk, 128, gru_smem>>>(bhh);
        dim3 pgrid(nblk, do_proj ? 2 : 1);
        k_post<<<pgrid, 128>>>(toW1, frW1, dec1, decb1, dec2, decb2, y,
                               (step == 3) ? out : nullptr, do_proj, step);
    }
    k_final<<<1, 32>>>(out);
}